// round 1
// baseline (speedup 1.0000x reference)
#include <cuda_runtime.h>

#define Bn 512
#define Cn 256
#define Ln 256
#define Hn 512
#define Tn 16
#define Wn 8
#define NU (Tn + Wn - 1)   // 23 distinct encode slices

// ---------------- scratch (device globals; no allocation) ----------------
__device__ float g_pred[Tn * Wn * Bn * Cn];      // [z=(t*W+w)][a][c]   64 MB
__device__ float g_Eg[NU * Bn * Cn];             // [u][b][c]           12 MB
__device__ float g_scores[Tn * Wn * Bn * Bn];    // [z][b][a]          128 MB
__device__ float g_h1[Bn * Wn * (Cn / 2)];       // [4096][128]          2 MB
__device__ float g_mean[Cn / 2];
__device__ float g_rstd[Cn / 2];
__device__ float g_part[8192];

// ---------------- gather: Eg[u][b][c] = features[b][c][base+u] ----------------
__global__ void gather_k(const float* __restrict__ f, const int* __restrict__ tptr) {
    int b = blockIdx.x;
    int c = threadIdx.x;  // blockDim = 256 = Cn
    int ts = *tptr;
    int base = min(ts + 1, Ln - Wn);
    const float* p = f + (size_t)b * Cn * Ln + (size_t)c * Ln;
#pragma unroll
    for (int u = 0; u < NU; u++) {
        float v = (base + u < Ln) ? p[base + u] : 0.f;
        g_Eg[(size_t)u * Bn * Cn + (size_t)b * Cn + c] = v;
    }
}

// ---------------- 128x128x(K) NT SGEMM tile, 256 threads, 8x8/thread ----------------
__device__ __forceinline__ void sgemm_128x128(
    const float* __restrict__ A, int lda,
    const float* __restrict__ B, int ldb,
    float* __restrict__ C, int ldc,
    const float* __restrict__ bias, int K)
{
    __shared__ float As[8][128];
    __shared__ float Bs[8][128];
    int tid = threadIdx.x;
    int lrow = tid >> 1;            // 0..127
    int lcol = (tid & 1) << 2;      // 0 or 4
    int ty = tid >> 4;              // 0..15
    int tx = tid & 15;              // 0..15

    float acc[8][8];
#pragma unroll
    for (int i = 0; i < 8; i++)
#pragma unroll
        for (int j = 0; j < 8; j++) acc[i][j] = 0.f;

    const float* Aptr = A + (size_t)lrow * lda + lcol;
    const float* Bptr = B + (size_t)lrow * ldb + lcol;

    for (int kb = 0; kb < K; kb += 8) {
        float4 a4 = *(const float4*)(Aptr + kb);
        float4 b4 = *(const float4*)(Bptr + kb);
        As[lcol + 0][lrow] = a4.x;
        As[lcol + 1][lrow] = a4.y;
        As[lcol + 2][lrow] = a4.z;
        As[lcol + 3][lrow] = a4.w;
        Bs[lcol + 0][lrow] = b4.x;
        Bs[lcol + 1][lrow] = b4.y;
        Bs[lcol + 2][lrow] = b4.z;
        Bs[lcol + 3][lrow] = b4.w;
        __syncthreads();
#pragma unroll
        for (int k = 0; k < 8; k++) {
            float af[8], bf[8];
#pragma unroll
            for (int i = 0; i < 8; i++) af[i] = As[k][ty * 8 + i];
#pragma unroll
            for (int j = 0; j < 8; j++) bf[j] = Bs[k][tx * 8 + j];
#pragma unroll
            for (int i = 0; i < 8; i++)
#pragma unroll
                for (int j = 0; j < 8; j++) acc[i][j] += af[i] * bf[j];
        }
        __syncthreads();
    }

#pragma unroll
    for (int i = 0; i < 8; i++) {
        int row = ty * 8 + i;
#pragma unroll
        for (int j = 0; j < 8; j += 4) {
            int col = tx * 8 + j;
            float4 v;
            v.x = acc[i][j + 0] + (bias ? bias[col + 0] : 0.f);
            v.y = acc[i][j + 1] + (bias ? bias[col + 1] : 0.f);
            v.z = acc[i][j + 2] + (bias ? bias[col + 2] : 0.f);
            v.w = acc[i][j + 3] + (bias ? bias[col + 3] : 0.f);
            *(float4*)(C + (size_t)row * ldc + col) = v;
        }
    }
}

// ---------------- pred[z][a][c] = c_t[a,w,:] . Wk_w[t,c,:] + Wk_b[t,c] ----------------
__global__ void pred_k(const float* __restrict__ ct, const float* __restrict__ Wk,
                       const float* __restrict__ Wb) {
    int z = blockIdx.z;
    int t = z / Wn, w = z % Wn;
    const float* A = ct + (size_t)blockIdx.y * 128 * (Wn * Hn) + (size_t)w * Hn;
    const float* Bp = Wk + (size_t)t * Cn * Hn + (size_t)blockIdx.x * 128 * Hn;
    float* Cp = g_pred + (size_t)z * Bn * Cn + (size_t)blockIdx.y * 128 * Cn + blockIdx.x * 128;
    sgemm_128x128(A, Wn * Hn, Bp, Hn, Cp, Cn, Wb + (size_t)t * Cn + blockIdx.x * 128, Hn);
}

// ---------------- scores[z][b][a] = Eg[u][b][:] . pred[z][a][:] ----------------
__global__ void scores_k(const int* __restrict__ tptr) {
    int z = blockIdx.z;
    int t = z / Wn, w = z % Wn;
    int ts = *tptr;
    int base = min(ts + 1, Ln - Wn);
    int u = min(ts + 1 + t, Ln - Wn) - base + w;
    const float* A = g_Eg + (size_t)u * Bn * Cn + (size_t)blockIdx.y * 128 * Cn;
    const float* Bp = g_pred + (size_t)z * Bn * Cn + (size_t)blockIdx.x * 128 * Cn;
    float* Cp = g_scores + (size_t)z * Bn * Bn + (size_t)blockIdx.y * 128 * Bn + blockIdx.x * 128;
    sgemm_128x128(A, Cn, Bp, Cn, Cp, Bn, nullptr, Cn);
}

// ---------------- h1 = c_t.reshape(4096,512) @ pw1^T + pb1 ----------------
__global__ void h1_k(const float* __restrict__ ct, const float* __restrict__ pw1,
                     const float* __restrict__ pb1) {
    const float* A = ct + (size_t)blockIdx.y * 128 * Hn;
    float* Cp = g_h1 + (size_t)blockIdx.y * 128 * (Cn / 2);
    sgemm_128x128(A, Hn, pw1, Hn, Cp, Cn / 2, pb1, Hn);
}

// ---------------- per-row logsumexp + diag, partial sums ----------------
__global__ void nce_rows_k() {
    __shared__ float sacc[8];
    int warp = threadIdx.x >> 5, lane = threadIdx.x & 31;
    int row = blockIdx.x * 8 + warp;  // 0..65535
    const float* s = g_scores + (size_t)row * Bn;
    float x[16];
    float m = -1e30f;
#pragma unroll
    for (int i = 0; i < 16; i++) {
        x[i] = s[lane + 32 * i];
        m = fmaxf(m, x[i]);
    }
#pragma unroll
    for (int o = 16; o; o >>= 1) m = fmaxf(m, __shfl_xor_sync(0xFFFFFFFFu, m, o));
    float sum = 0.f;
#pragma unroll
    for (int i = 0; i < 16; i++) sum += expf(x[i] - m);
#pragma unroll
    for (int o = 16; o; o >>= 1) sum += __shfl_xor_sync(0xFFFFFFFFu, sum, o);
    if (lane == 0) {
        int b = row & (Bn - 1);
        float d = s[b];
        sacc[warp] = d - m - logf(sum);
    }
    __syncthreads();
    if (threadIdx.x == 0) {
        float t = 0.f;
#pragma unroll
        for (int i = 0; i < 8; i++) t += sacc[i];
        g_part[blockIdx.x] = t;
    }
}

__global__ void nce_final_k(float* __restrict__ out) {
    __shared__ float sm[256];
    float a = 0.f;
    for (int i = threadIdx.x; i < 8192; i += 256) a += g_part[i];
    sm[threadIdx.x] = a;
    __syncthreads();
    for (int o = 128; o; o >>= 1) {
        if (threadIdx.x < o) sm[threadIdx.x] += sm[threadIdx.x + o];
        __syncthreads();
    }
    if (threadIdx.x == 0) out[0] = -sm[0] / (float)(Bn * Tn * Wn);
}

// ---------------- BatchNorm train stats per channel ----------------
__global__ void bn_k() {
    int j = blockIdx.x;
    float s1 = 0.f, s2 = 0.f;
    for (int i = threadIdx.x; i < Bn * Wn; i += 256) {
        float v = g_h1[(size_t)i * (Cn / 2) + j];
        s1 += v;
        s2 += v * v;
    }
    __shared__ float a1[256], a2[256];
    a1[threadIdx.x] = s1;
    a2[threadIdx.x] = s2;
    __syncthreads();
    for (int o = 128; o; o >>= 1) {
        if (threadIdx.x < o) {
            a1[threadIdx.x] += a1[threadIdx.x + o];
            a2[threadIdx.x] += a2[threadIdx.x + o];
        }
        __syncthreads();
    }
    if (threadIdx.x == 0) {
        float mean = a1[0] / (float)(Bn * Wn);
        float var = a2[0] / (float)(Bn * Wn) - mean * mean;
        g_mean[j] = mean;
        g_rstd[j] = rsqrtf(var + 1e-5f);
    }
}

// ---------------- normalize + relu + second linear -> proj ----------------
__global__ void proj_k(const float* __restrict__ gamma, const float* __restrict__ beta,
                       const float* __restrict__ pw2, const float* __restrict__ pb2,
                       float* __restrict__ out) {
    __shared__ float sm[Cn / 2];
    int i = blockIdx.x, t = threadIdx.x;  // blockDim = 64
#pragma unroll
    for (int r = 0; r < 2; r++) {
        int j = t + r * 64;
        float v = g_h1[(size_t)i * (Cn / 2) + j];
        v = (v - g_mean[j]) * g_rstd[j] * gamma[j] + beta[j];
        sm[j] = fmaxf(v, 0.f);
    }
    __syncthreads();
    float acc = pb2[t];
    const float* wrow = pw2 + (size_t)t * (Cn / 2);
#pragma unroll 8
    for (int jj = 0; jj < Cn / 2; jj++) acc += sm[jj] * wrow[jj];
    out[1 + (size_t)i * 64 + t] = acc;
}

// ---------------- launch ----------------
extern "C" void kernel_launch(void* const* d_in, const int* in_sizes, int n_in,
                              void* d_out, int out_size) {
    const float* features = (const float*)d_in[0];
    const float* c_t      = (const float*)d_in[1];
    const float* Wk_w     = (const float*)d_in[2];
    const float* Wk_b     = (const float*)d_in[3];
    const float* pw1      = (const float*)d_in[4];
    const float* pb1      = (const float*)d_in[5];
    const float* gamma    = (const float*)d_in[6];
    const float* beta     = (const float*)d_in[7];
    const float* pw2      = (const float*)d_in[8];
    const float* pb2      = (const float*)d_in[9];
    const int*   tptr     = (const int*)d_in[10];
    float* out = (float*)d_out;

    gather_k<<<Bn, Cn>>>(features, tptr);
    pred_k<<<dim3(Cn / 128, Bn / 128, Tn * Wn), 256>>>(c_t, Wk_w, Wk_b);
    h1_k<<<dim3(1, (Bn * Wn) / 128, 1), 256>>>(c_t, pw1, pb1);
    scores_k<<<dim3(Bn / 128, Bn / 128, Tn * Wn), 256>>>(tptr);
    nce_rows_k<<<(Tn * Wn * Bn) / 8, 256>>>();
    nce_final_k<<<1, 256>>>(out);
    bn_k<<<Cn / 2, 256>>>();
    proj_k<<<Bn * Wn, 64>>>(gamma, beta, pw2, pb2, out);
}

// round 3
// speedup vs baseline: 1.7194x; 1.7194x over previous
#include <cuda_runtime.h>
#include <cuda_bf16.h>
#include <cstdint>

#define Bn 512
#define Cn 256
#define Ln 256
#define Hn 512
#define Tn 16
#define Wn 8
#define NU (Tn + Wn - 1)   // 23 distinct encode slices
#define Zn (Tn * Wn)       // 128

// ---------------- scratch (device globals; no allocation) ----------------
// Concatenated-K operands for split-bf16 emulated-fp32 GEMM.
// ct_cat [4096][1536]: cols [0,512)=hi, [512,1024)=hi, [1024,1536)=lo
// wk_cat [4096][1536]: cols [0,512)=hi, [512,1024)=lo, [1024,1536)=hi
// E_cat  [23][512][768]: cols [0,256)=hi, [256,512)=hi, [512,768)=lo
// P_cat  [128][512][768]: cols [0,256)=hi, [256,512)=lo, [512,768)=hi
__device__ __align__(256) __nv_bfloat16 g_ct_cat[Bn * Wn * 3 * Hn];
__device__ __align__(256) __nv_bfloat16 g_wk_cat[Tn * Cn * 3 * Hn];
__device__ __align__(256) __nv_bfloat16 g_E_cat[NU * Bn * 3 * Cn];
__device__ __align__(256) __nv_bfloat16 g_P_cat[(size_t)Zn * Bn * 3 * Cn];
__device__ float g_pm[(size_t)Zn * 4 * Bn];   // per (z, atile, b) partial max
__device__ float g_ps[(size_t)Zn * 4 * Bn];   // per (z, atile, b) partial sumexp
__device__ float g_diag[(size_t)Zn * Bn];
__device__ float g_h1[Bn * Wn * (Cn / 2)];
__device__ float g_mean[Cn / 2];
__device__ float g_rstd[Cn / 2];
__device__ float g_part[256];

// ======================= helpers =======================
__device__ __forceinline__ uint32_t smem_to_u32(const void* p) {
    uint32_t a;
    asm("{ .reg .u64 t; cvta.to.shared.u64 t, %1; cvt.u32.u64 %0, t; }" : "=r"(a) : "l"(p));
    return a;
}
__device__ __forceinline__ void cp16(uint32_t s, const void* g) {
    asm volatile("cp.async.cg.shared.global [%0], [%1], 16;" :: "r"(s), "l"(g));
}
__device__ __forceinline__ void ldsm4(uint32_t* r, uint32_t addr) {
    asm volatile("ldmatrix.sync.aligned.m8n8.x4.shared.b16 {%0,%1,%2,%3}, [%4];"
        : "=r"(r[0]), "=r"(r[1]), "=r"(r[2]), "=r"(r[3]) : "r"(addr));
}
__device__ __forceinline__ void mma16816(float* d, const uint32_t* a, uint32_t b0, uint32_t b1) {
    asm volatile("mma.sync.aligned.m16n8k16.row.col.f32.bf16.bf16.f32 "
        "{%0,%1,%2,%3}, {%4,%5,%6,%7}, {%8,%9}, {%0,%1,%2,%3};"
        : "+f"(d[0]), "+f"(d[1]), "+f"(d[2]), "+f"(d[3])
        : "r"(a[0]), "r"(a[1]), "r"(a[2]), "r"(a[3]), "r"(b0), "r"(b1));
}
__device__ __forceinline__ uint32_t pack_bf2(__nv_bfloat16 lo, __nv_bfloat16 hi) {
    return (uint32_t)__bfloat16_as_ushort(lo) | ((uint32_t)__bfloat16_as_ushort(hi) << 16);
}

// smem tile geometry: rows of 32 bf16 (64B) padded to 80B; 128 rows = 10240B per tile
#define ROWB 80
#define TILEB 10240
// layout: A0 @0, A1 @10240, B0 @20480, B1 @30720  (total 40960)

// ======================= generic NT bf16 GEMM mainloop =======================
// C[128m x 128n] += A[m, k'] * B[n, k'], k' = nch*32, NT (both K-contiguous).
__device__ __forceinline__ void gemm_mainloop(
    const __nv_bfloat16* __restrict__ baseA, int strideA,
    const __nv_bfloat16* __restrict__ baseB, int strideB,
    int nch, uint32_t smb, float (&acc)[4][4][4])
{
    int tid = threadIdx.x;
    int lane = tid & 31, warp = tid >> 5;
    int wm = warp >> 2, wn = warp & 3;

#pragma unroll
    for (int mt = 0; mt < 4; mt++)
#pragma unroll
        for (int j = 0; j < 4; j++)
#pragma unroll
            for (int q = 0; q < 4; q++) acc[mt][j][q] = 0.f;

    int rseg = tid >> 2, qseg = tid & 3;          // segment owner: 2 segs per tile
    int rseg2 = (tid + 256) >> 2, qseg2 = (tid + 256) & 3;

#define ISSUE_CHUNK(ch, buf) do { \
    int kofs = (ch) * 32; \
    cp16(smb + (buf) * TILEB + rseg * ROWB + qseg * 16, \
         baseA + (size_t)rseg * strideA + kofs + qseg * 8); \
    cp16(smb + (buf) * TILEB + rseg2 * ROWB + qseg2 * 16, \
         baseA + (size_t)rseg2 * strideA + kofs + qseg2 * 8); \
    cp16(smb + 20480 + (buf) * TILEB + rseg * ROWB + qseg * 16, \
         baseB + (size_t)rseg * strideB + kofs + qseg * 8); \
    cp16(smb + 20480 + (buf) * TILEB + rseg2 * ROWB + qseg2 * 16, \
         baseB + (size_t)rseg2 * strideB + kofs + qseg2 * 8); \
    asm volatile("cp.async.commit_group;"); \
} while (0)

    ISSUE_CHUNK(0, 0);
    for (int ch = 0; ch < nch; ch++) {
        int buf = ch & 1;
        if (ch + 1 < nch) {
            ISSUE_CHUNK(ch + 1, buf ^ 1);
            asm volatile("cp.async.wait_group 1;");
        } else {
            asm volatile("cp.async.wait_group 0;");
        }
        __syncthreads();
        uint32_t A0 = smb + buf * TILEB;
        uint32_t B0 = smb + 20480 + buf * TILEB;
#pragma unroll
        for (int kk = 0; kk < 2; kk++) {
            uint32_t af[4][4];
#pragma unroll
            for (int mt = 0; mt < 4; mt++) {
                uint32_t ad = A0 + (wm * 64 + mt * 16 + (lane & 15)) * ROWB
                            + (kk * 16 + (lane >> 4) * 8) * 2;
                ldsm4(af[mt], ad);
            }
            uint32_t bf[2][4];
#pragma unroll
            for (int nt = 0; nt < 2; nt++) {
                int rowb = wn * 32 + nt * 16 + (lane & 7) + ((lane >> 4) << 3);
                int colb = ((lane >> 3) & 1) * 8 + kk * 16;
                ldsm4(bf[nt], B0 + rowb * ROWB + colb * 2);
            }
#pragma unroll
            for (int mt = 0; mt < 4; mt++)
#pragma unroll
                for (int j = 0; j < 4; j++) {
                    int nt = j >> 1, h = j & 1;
                    mma16816(acc[mt][j], af[mt], bf[nt][2 * h], bf[nt][2 * h + 1]);
                }
        }
        __syncthreads();
    }
#undef ISSUE_CHUNK
}

// ======================= conversion kernels =======================
__global__ void split_ct_k(const float* __restrict__ src) {   // [4096][512]
    int i = blockIdx.x * 256 + threadIdx.x;
    int row = i >> 9, col = i & 511;
    float x = src[i];
    __nv_bfloat16 h = __float2bfloat16(x);
    __nv_bfloat16 l = __float2bfloat16(x - __bfloat162float(h));
    size_t o = (size_t)row * 1536 + col;
    g_ct_cat[o] = h; g_ct_cat[o + 512] = h; g_ct_cat[o + 1024] = l;
}
__global__ void split_wk_k(const float* __restrict__ src) {   // [4096][512]
    int i = blockIdx.x * 256 + threadIdx.x;
    int row = i >> 9, col = i & 511;
    float x = src[i];
    __nv_bfloat16 h = __float2bfloat16(x);
    __nv_bfloat16 l = __float2bfloat16(x - __bfloat162float(h));
    size_t o = (size_t)row * 1536 + col;
    g_wk_cat[o] = h; g_wk_cat[o + 512] = l; g_wk_cat[o + 1024] = h;
}
__global__ void gather_split_k(const float* __restrict__ f, const int* __restrict__ tptr) {
    int b = blockIdx.x;
    int c = threadIdx.x;  // 256
    int ts = *tptr;
    int base = min(ts + 1, Ln - Wn);
    const float* p = f + (size_t)b * Cn * Ln + (size_t)c * Ln;
#pragma unroll
    for (int u = 0; u < NU; u++) {
        float v = (base + u < Ln) ? p[base + u] : 0.f;
        __nv_bfloat16 h = __float2bfloat16(v);
        __nv_bfloat16 l = __float2bfloat16(v - __bfloat162float(h));
        size_t o = ((size_t)u * Bn + b) * 768 + c;
        g_E_cat[o] = h; g_E_cat[o + 256] = h; g_E_cat[o + 512] = l;
    }
}

// ======================= pred GEMM =======================
// per z=(t,w): P[a, c] = ct[a,w,:] . Wk[t,c,:] + Wk_b[t,c]   (M=512 a, N=256 c, K'=1536)
__global__ __launch_bounds__(256) void pred_g(const float* __restrict__ Wkb) {
    __shared__ __align__(16) char sm[40960];
    int bx = blockIdx.x;   // c tile 0..1
    int by = blockIdx.y;   // a tile 0..3
    int z = blockIdx.z;
    int t = z >> 3, w = z & 7;
    const __nv_bfloat16* baseA = g_ct_cat + ((size_t)(by * 128) * 8 + w) * 1536;
    const __nv_bfloat16* baseB = g_wk_cat + (size_t)(t * 256 + bx * 128) * 1536;
    float acc[4][4][4];
    gemm_mainloop(baseA, 8 * 1536, baseB, 1536, 48, smem_to_u32(sm), acc);

    int lane = threadIdx.x & 31, warp = threadIdx.x >> 5;
    int wm = warp >> 2, wn = warp & 3;
    uint32_t* P = (uint32_t*)g_P_cat;
#pragma unroll
    for (int mt = 0; mt < 4; mt++) {
#pragma unroll
        for (int j = 0; j < 4; j++) {
            int a0 = by * 128 + wm * 64 + mt * 16 + (lane >> 2);
            int c  = bx * 128 + wn * 32 + j * 8 + (lane & 3) * 2;
            float bb0 = Wkb[t * 256 + c], bb1 = Wkb[t * 256 + c + 1];
#pragma unroll
            for (int h = 0; h < 2; h++) {
                int a = a0 + h * 8;
                float v0 = acc[mt][j][h * 2 + 0] + bb0;
                float v1 = acc[mt][j][h * 2 + 1] + bb1;
                __nv_bfloat16 h0 = __float2bfloat16(v0);
                __nv_bfloat16 h1 = __float2bfloat16(v1);
                __nv_bfloat16 l0 = __float2bfloat16(v0 - __bfloat162float(h0));
                __nv_bfloat16 l1 = __float2bfloat16(v1 - __bfloat162float(h1));
                uint32_t hp = pack_bf2(h0, h1), lp = pack_bf2(l0, l1);
                size_t e = ((size_t)z * 512 + a) * 768 + c;
                P[e >> 1] = hp;
                P[(e + 256) >> 1] = lp;
                P[(e + 512) >> 1] = hp;
            }
        }
    }
}

// ======================= scores GEMM + fused softmax partials =======================
// per z: S[b, a] = E[u][b,:] . P[z][a,:]   (M=512 b, N=512 a, K'=768)
__global__ __launch_bounds__(256) void scores_g(const int* __restrict__ tptr) {
    __shared__ __align__(16) char sm[40960];
    int bx = blockIdx.x;   // a tile 0..3
    int by = blockIdx.y;   // b tile 0..3
    int z = blockIdx.z;
    int t = z >> 3, w = z & 7;
    int ts = *tptr;
    int base = min(ts + 1, Ln - Wn);
    int u = min(ts + 1 + t, Ln - Wn) - base + w;
    const __nv_bfloat16* baseA = g_E_cat + ((size_t)u * 512 + by * 128) * 768;
    const __nv_bfloat16* baseB = g_P_cat + ((size_t)z * 512 + bx * 128) * 768;
    float acc[4][4][4];
    gemm_mainloop(baseA, 768, baseB, 768, 24, smem_to_u32(sm), acc);

    int tid = threadIdx.x;
    int lane = tid & 31, warp = tid >> 5;
    int wm = warp >> 2, wn = warp & 3;
    float* smx = (float*)sm;            // [4][128]
    float* sms = (float*)(sm + 2048);   // [4][128]
    __syncthreads();
#pragma unroll
    for (int mt = 0; mt < 4; mt++) {
#pragma unroll
        for (int h = 0; h < 2; h++) {
            int row = wm * 64 + mt * 16 + h * 8 + (lane >> 2);
            float mx = -1e30f;
#pragma unroll
            for (int j = 0; j < 4; j++)
                mx = fmaxf(mx, fmaxf(acc[mt][j][h * 2], acc[mt][j][h * 2 + 1]));
            mx = fmaxf(mx, __shfl_xor_sync(0xFFFFFFFFu, mx, 1));
            mx = fmaxf(mx, __shfl_xor_sync(0xFFFFFFFFu, mx, 2));
            float s = 0.f;
#pragma unroll
            for (int j = 0; j < 4; j++) {
                s += __expf(acc[mt][j][h * 2] - mx);
                s += __expf(acc[mt][j][h * 2 + 1] - mx);
            }
            s += __shfl_xor_sync(0xFFFFFFFFu, s, 1);
            s += __shfl_xor_sync(0xFFFFFFFFu, s, 2);
            if ((lane & 3) == 0) { smx[wn * 128 + row] = mx; sms[wn * 128 + row] = s; }
            if (bx == by) {
#pragma unroll
                for (int j = 0; j < 4; j++) {
                    int col = wn * 32 + j * 8 + (lane & 3) * 2;
                    if (col == row)
                        g_diag[(size_t)z * 512 + by * 128 + row] = acc[mt][j][h * 2];
                    else if (col + 1 == row)
                        g_diag[(size_t)z * 512 + by * 128 + row] = acc[mt][j][h * 2 + 1];
                }
            }
        }
    }
    __syncthreads();
    if (tid < 128) {
        float m0 = smx[tid], m1 = smx[128 + tid], m2 = smx[256 + tid], m3 = smx[384 + tid];
        float M = fmaxf(fmaxf(m0, m1), fmaxf(m2, m3));
        float S = sms[tid] * __expf(m0 - M) + sms[128 + tid] * __expf(m1 - M)
                + sms[256 + tid] * __expf(m2 - M) + sms[384 + tid] * __expf(m3 - M);
        size_t o = ((size_t)z * 4 + bx) * 512 + by * 128 + tid;
        g_pm[o] = M;
        g_ps[o] = S;
    }
}

// ======================= NCE reduction =======================
__global__ void nce_combine_k() {
    int idx = blockIdx.x * 256 + threadIdx.x;   // z*512 + b
    int z = idx >> 9, b = idx & 511;
    float M = -1e30f;
#pragma unroll
    for (int i = 0; i < 4; i++) M = fmaxf(M, g_pm[((size_t)z * 4 + i) * 512 + b]);
    float S = 0.f;
#pragma unroll
    for (int i = 0; i < 4; i++)
        S += g_ps[((size_t)z * 4 + i) * 512 + b] * expf(g_pm[((size_t)z * 4 + i) * 512 + b] - M);
    float term = g_diag[idx] - (M + logf(S));
    __shared__ float smr[256];
    smr[threadIdx.x] = term;
    __syncthreads();
    for (int o = 128; o; o >>= 1) {
        if (threadIdx.x < o) smr[threadIdx.x] += smr[threadIdx.x + o];
        __syncthreads();
    }
    if (threadIdx.x == 0) g_part[blockIdx.x] = smr[0];
}

__global__ void nce_final_k(float* __restrict__ out) {
    __shared__ float smr[256];
    smr[threadIdx.x] = g_part[threadIdx.x];
    __syncthreads();
    for (int o = 128; o; o >>= 1) {
        if (threadIdx.x < o) smr[threadIdx.x] += smr[threadIdx.x + o];
        __syncthreads();
    }
    if (threadIdx.x == 0) out[0] = -smr[0] / (float)(Bn * Tn * Wn);
}

// ======================= projection head (fp32) =======================
__device__ __forceinline__ void sgemm_128x128(
    const float* __restrict__ A, int lda,
    const float* __restrict__ B, int ldb,
    float* __restrict__ C, int ldc,
    const float* __restrict__ bias, int K)
{
    __shared__ float As[8][128];
    __shared__ float Bs[8][128];
    int tid = threadIdx.x;
    int lrow = tid >> 1;
    int lcol = (tid & 1) << 2;
    int ty = tid >> 4;
    int tx = tid & 15;
    float acc[8][8];
#pragma unroll
    for (int i = 0; i < 8; i++)
#pragma unroll
        for (int j = 0; j < 8; j++) acc[i][j] = 0.f;
    const float* Aptr = A + (size_t)lrow * lda + lcol;
    const float* Bptr = B + (size_t)lrow * ldb + lcol;
    for (int kb = 0; kb < K; kb += 8) {
        float4 a4 = *(const float4*)(Aptr + kb);
        float4 b4 = *(const float4*)(Bptr + kb);
        As[lcol + 0][lrow] = a4.x; As[lcol + 1][lrow] = a4.y;
        As[lcol + 2][lrow] = a4.z; As[lcol + 3][lrow] = a4.w;
        Bs[lcol + 0][lrow] = b4.x; Bs[lcol + 1][lrow] = b4.y;
        Bs[lcol + 2][lrow] = b4.z; Bs[lcol + 3][lrow] = b4.w;
        __syncthreads();
#pragma unroll
        for (int k = 0; k < 8; k++) {
            float af[8], bf2[8];
#pragma unroll
            for (int i = 0; i < 8; i++) af[i] = As[k][ty * 8 + i];
#pragma unroll
            for (int j = 0; j < 8; j++) bf2[j] = Bs[k][tx * 8 + j];
#pragma unroll
            for (int i = 0; i < 8; i++)
#pragma unroll
                for (int j = 0; j < 8; j++) acc[i][j] += af[i] * bf2[j];
        }
        __syncthreads();
    }
#pragma unroll
    for (int i = 0; i < 8; i++) {
        int row = ty * 8 + i;
#pragma unroll
        for (int j = 0; j < 8; j += 4) {
            int col = tx * 8 + j;
            float4 v;
            v.x = acc[i][j + 0] + bias[col + 0];
            v.y = acc[i][j + 1] + bias[col + 1];
            v.z = acc[i][j + 2] + bias[col + 2];
            v.w = acc[i][j + 3] + bias[col + 3];
            *(float4*)(C + (size_t)row * ldc + col) = v;
        }
    }
}

__global__ void h1_k(const float* __restrict__ ct, const float* __restrict__ pw1,
                     const float* __restrict__ pb1) {
    const float* A = ct + (size_t)blockIdx.y * 128 * Hn;
    float* Cp = g_h1 + (size_t)blockIdx.y * 128 * (Cn / 2);
    sgemm_128x128(A, Hn, pw1, Hn, Cp, Cn / 2, pb1, Hn);
}

__global__ void bn_k() {
    int j = blockIdx.x;
    float s1 = 0.f, s2 = 0.f;
    for (int i = threadIdx.x; i < Bn * Wn; i += 256) {
        float v = g_h1[(size_t)i * (Cn / 2) + j];
        s1 += v; s2 += v * v;
    }
    __shared__ float a1[256], a2[256];
    a1[threadIdx.x] = s1; a2[threadIdx.x] = s2;
    __syncthreads();
    for (int o = 128; o; o >>= 1) {
        if (threadIdx.x < o) { a1[threadIdx.x] += a1[threadIdx.x + o]; a2[threadIdx.x] += a2[threadIdx.x + o]; }
        __syncthreads();
    }
    if (threadIdx.x == 0) {
        float mean = a1[0] / (float)(Bn * Wn);
        float var = a2[0] / (float)(Bn * Wn) - mean * mean;
        g_mean[j] = mean;
        g_rstd[j] = rsqrtf(var + 1e-5f);
    }
}

__global__ void proj_k(const float* __restrict__ gamma, const float* __restrict__ beta,
                       const float* __restrict__ pw2, const float* __restrict__ pb2,
                       float* __restrict__ out) {
    __shared__ float smr[Cn / 2];
    int i = blockIdx.x, t = threadIdx.x;  // blockDim = 64
#pragma unroll
    for (int r = 0; r < 2; r++) {
        int j = t + r * 64;
        float v = g_h1[(size_t)i * (Cn / 2) + j];
        v = (v - g_mean[j]) * g_rstd[j] * gamma[j] + beta[j];
        smr[j] = fmaxf(v, 0.f);
    }
    __syncthreads();
    float acc = pb2[t];
    const float* wrow = pw2 + (size_t)t * (Cn / 2);
#pragma unroll 8
    for (int jj = 0; jj < Cn / 2; jj++) acc += smr[jj] * wrow[jj];
    out[1 + (size_t)i * 64 + t] = acc;
}

// ======================= launch =======================
extern "C" void kernel_launch(void* const* d_in, const int* in_sizes, int n_in,
                              void* d_out, int out_size) {
    const float* features = (const float*)d_in[0];
    const float* c_t      = (const float*)d_in[1];
    const float* Wk_w     = (const float*)d_in[2];
    const float* Wk_b     = (const float*)d_in[3];
    const float* pw1      = (const float*)d_in[4];
    const float* pb1      = (const float*)d_in[5];
    const float* gamma    = (const float*)d_in[6];
    const float* beta     = (const float*)d_in[7];
    const float* pw2      = (const float*)d_in[8];
    const float* pb2      = (const float*)d_in[9];
    const int*   tptr     = (const int*)d_in[10];
    float* out = (float*)d_out;

    split_ct_k<<<(Bn * Wn * Hn) / 256, 256>>>(c_t);
    split_wk_k<<<(Tn * Cn * Hn) / 256, 256>>>(Wk_w);
    gather_split_k<<<Bn, Cn>>>(features, tptr);
    h1_k<<<dim3(1, (Bn * Wn) / 128), 256>>>(c_t, pw1, pb1);

    pred_g<<<dim3(2, 4, Zn), 256>>>(Wk_b);
    scores_g<<<dim3(4, 4, Zn), 256>>>(tptr);

    nce_combine_k<<<256, 256>>>();
    nce_final_k<<<1, 256>>>(out);
    bn_k<<<Cn / 2, 256>>>();
    proj_k<<<Bn * Wn, 64>>>(gamma, beta, pw2, pb2, out);
}

// round 4
// speedup vs baseline: 1.8841x; 1.0958x over previous
#include <cuda_runtime.h>
#include <cuda_bf16.h>
#include <cstdint>

#define Bn 512
#define Cn 256
#define Ln 256
#define Hn 512
#define Tn 16
#define Wn 8
#define NU (Tn + Wn - 1)   // 23 distinct encode slices
#define Zn (Tn * Wn)       // 128

// ---------------- scratch (device globals; dedup [hi|lo] storage) ----------------
// ct_cat [4096][1024]: cols [0,512)=hi, [512,1024)=lo     (logical K'=1536: hi,hi,lo)
// wk_cat [4096][1024]: same storage                        (logical: hi,lo,hi)
// pw1_cat [128][1024]                                      (logical: hi,lo,hi)
// E_cat  [23*512][512]: [0,256)=hi, [256,512)=lo           (logical K'=768: hi,hi,lo)
// P_cat  [128*512][512]: same                              (logical: hi,lo,hi)
__device__ __align__(256) __nv_bfloat16 g_ct_cat[Bn * Wn * 1024];
__device__ __align__(256) __nv_bfloat16 g_wk_cat[Tn * Cn * 1024];
__device__ __align__(256) __nv_bfloat16 g_pw1_cat[128 * 1024];
__device__ __align__(256) __nv_bfloat16 g_E_cat[NU * Bn * 512];
__device__ __align__(256) __nv_bfloat16 g_P_cat[(size_t)Zn * Bn * 512];
__device__ float g_pm[(size_t)Zn * 2 * Bn];
__device__ float g_ps[(size_t)Zn * 2 * Bn];
__device__ float g_diag[(size_t)Zn * Bn];
__device__ float g_h1[Bn * Wn * (Cn / 2)];
__device__ float g_mean[Cn / 2];
__device__ float g_rstd[Cn / 2];
__device__ float g_part[256];

// ======================= helpers =======================
__device__ __forceinline__ uint32_t smem_to_u32(const void* p) {
    uint32_t a;
    asm("{ .reg .u64 t; cvta.to.shared.u64 t, %1; cvt.u32.u64 %0, t; }" : "=r"(a) : "l"(p));
    return a;
}
__device__ __forceinline__ void cp16(uint32_t s, const void* g) {
    asm volatile("cp.async.cg.shared.global [%0], [%1], 16;" :: "r"(s), "l"(g));
}
__device__ __forceinline__ void ldsm4(uint32_t* r, uint32_t addr) {
    asm volatile("ldmatrix.sync.aligned.m8n8.x4.shared.b16 {%0,%1,%2,%3}, [%4];"
        : "=r"(r[0]), "=r"(r[1]), "=r"(r[2]), "=r"(r[3]) : "r"(addr));
}
__device__ __forceinline__ void mma16816(float* d, const uint32_t* a, uint32_t b0, uint32_t b1) {
    asm volatile("mma.sync.aligned.m16n8k16.row.col.f32.bf16.bf16.f32 "
        "{%0,%1,%2,%3}, {%4,%5,%6,%7}, {%8,%9}, {%0,%1,%2,%3};"
        : "+f"(d[0]), "+f"(d[1]), "+f"(d[2]), "+f"(d[3])
        : "r"(a[0]), "r"(a[1]), "r"(a[2]), "r"(a[3]), "r"(b0), "r"(b1));
}

struct RemapH16 { __device__ int operator()(int c) const { return c < 16 ? c : c - 16; } };
struct RemapH32 { __device__ int operator()(int c) const { return c < 32 ? c : c - 32; } };
struct RemapH8  { __device__ int operator()(int c) const { return c < 8  ? c : c - 8;  } };

// rows of 32 bf16 (64B) padded to 80B -> conflict-free ldmatrix
#define ROWB 80

// ======================= templated GEMM core =======================
// C[128 x NB] += A[128, K'] * B[NB, K'] (NT), K' = NCH*32, 4-stage cp.async pipeline.
// acc layout: [mt 0..3][j 0..NB/32-1][4], warp tile 64 x (NB/4).
template<int NCH, int NB, typename FA, typename FB>
__device__ __forceinline__ void gemm_core(
    const __nv_bfloat16* __restrict__ baseA, int strideA, FA remapA,
    const __nv_bfloat16* __restrict__ baseB, int strideB, FB remapB,
    char* smem, float (&acc)[4][NB / 32][4])
{
    constexpr int STAGE = (128 + NB) * ROWB;
    constexpr int NJ = NB / 32;       // n-frags per warp tile
    constexpr int NT = NB / 64;       // B ldsm.x4 per kk
    uint32_t smb = smem_to_u32(smem);
    int tid = threadIdx.x, lane = tid & 31, warp = tid >> 5;
    int wm = warp >> 2, wn = warp & 3;
    constexpr int WNW = NB / 4;       // warp n width

#pragma unroll
    for (int mt = 0; mt < 4; mt++)
#pragma unroll
        for (int j = 0; j < NJ; j++)
#pragma unroll
            for (int q = 0; q < 4; q++) acc[mt][j][q] = 0.f;

    auto issue = [&](int ch, int stg) {
        int ka = remapA(ch) * 32, kb = remapB(ch) * 32;
        uint32_t s0 = smb + stg * STAGE;
#pragma unroll
        for (int i = 0; i < 2; i++) {
            int idx = tid + 256 * i, r = idx >> 2, q = idx & 3;
            cp16(s0 + r * ROWB + q * 16, baseA + (size_t)r * strideA + ka + q * 8);
        }
#pragma unroll
        for (int i = 0; i < NB / 64; i++) {
            int idx = tid + 256 * i, r = idx >> 2, q = idx & 3;
            cp16(s0 + 128 * ROWB + r * ROWB + q * 16, baseB + (size_t)r * strideB + kb + q * 8);
        }
        asm volatile("cp.async.commit_group;");
    };

    issue(0, 0); issue(1, 1); issue(2, 2);
    for (int ch = 0; ch < NCH; ch++) {
        int stg = ch & 3;
        asm volatile("cp.async.wait_group 2;");
        __syncthreads();
        if (ch + 3 < NCH) issue(ch + 3, (ch + 3) & 3);
        else asm volatile("cp.async.commit_group;");
        uint32_t A0 = smb + stg * STAGE;
        uint32_t B0 = A0 + 128 * ROWB;
#pragma unroll
        for (int kk = 0; kk < 2; kk++) {
            uint32_t af[4][4];
#pragma unroll
            for (int mt = 0; mt < 4; mt++)
                ldsm4(af[mt], A0 + (wm * 64 + mt * 16 + (lane & 15)) * ROWB
                            + (kk * 16 + (lane >> 4) * 8) * 2);
            uint32_t bfr[NT][4];
#pragma unroll
            for (int nt = 0; nt < NT; nt++) {
                int rowb = wn * WNW + nt * 16 + (lane & 7) + ((lane >> 4) << 3);
                int colb = ((lane >> 3) & 1) * 8 + kk * 16;
                ldsm4(bfr[nt], B0 + rowb * ROWB + colb * 2);
            }
#pragma unroll
            for (int mt = 0; mt < 4; mt++)
#pragma unroll
                for (int j = 0; j < NJ; j++) {
                    int nt = j >> 1, h = j & 1;
                    mma16816(acc[mt][j], af[mt], bfr[nt][2 * h], bfr[nt][2 * h + 1]);
                }
        }
        __syncthreads();
    }
}

// ======================= conversion kernels =======================
__global__ void split_ct_k(const float* __restrict__ src) {   // [4096][512]
    int i = blockIdx.x * 256 + threadIdx.x;
    int row = i >> 9, col = i & 511;
    float x = src[i];
    __nv_bfloat16 h = __float2bfloat16(x);
    __nv_bfloat16 l = __float2bfloat16(x - __bfloat162float(h));
    size_t o = (size_t)row * 1024 + col;
    g_ct_cat[o] = h; g_ct_cat[o + 512] = l;
}
__global__ void split_wk_k(const float* __restrict__ src) {   // [4096][512]
    int i = blockIdx.x * 256 + threadIdx.x;
    int row = i >> 9, col = i & 511;
    float x = src[i];
    __nv_bfloat16 h = __float2bfloat16(x);
    __nv_bfloat16 l = __float2bfloat16(x - __bfloat162float(h));
    size_t o = (size_t)row * 1024 + col;
    g_wk_cat[o] = h; g_wk_cat[o + 512] = l;
}
__global__ void split_pw1_k(const float* __restrict__ src) {  // [128][512]
    int i = blockIdx.x * 256 + threadIdx.x;
    int row = i >> 9, col = i & 511;
    float x = src[i];
    __nv_bfloat16 h = __float2bfloat16(x);
    __nv_bfloat16 l = __float2bfloat16(x - __bfloat162float(h));
    size_t o = (size_t)row * 1024 + col;
    g_pw1_cat[o] = h; g_pw1_cat[o + 512] = l;
}
__global__ void gather_split_k(const float* __restrict__ f, const int* __restrict__ tptr) {
    int b = blockIdx.x;
    int c = threadIdx.x;  // 256
    int ts = *tptr;
    int base = min(ts + 1, Ln - Wn);
    const float* p = f + (size_t)b * Cn * Ln + (size_t)c * Ln;
#pragma unroll
    for (int u = 0; u < NU; u++) {
        float v = (base + u < Ln) ? p[base + u] : 0.f;
        __nv_bfloat16 h = __float2bfloat16(v);
        __nv_bfloat16 l = __float2bfloat16(v - __bfloat162float(h));
        size_t o = ((size_t)u * Bn + b) * 512 + c;
        g_E_cat[o] = h; g_E_cat[o + 256] = l;
    }
}

// ======================= pred GEMM (128x256, K'=1536) =======================
// per z=(t,w): P[a, c] = ct[a,w,:] . Wk[t,c,:] + Wk_b[t,c]
__global__ __launch_bounds__(256, 1) void pred_g(const float* __restrict__ Wkb) {
    extern __shared__ __align__(16) char sm[];
    int by = blockIdx.x;   // a tile 0..3
    int z = blockIdx.y;
    int t = z >> 3, w = z & 7;
    const __nv_bfloat16* baseA = g_ct_cat + ((size_t)(by * 128) * 8 + w) * 1024;
    const __nv_bfloat16* baseB = g_wk_cat + (size_t)(t * 256) * 1024;
    float acc[4][8][4];
    gemm_core<48, 256>(baseA, 8 * 1024, RemapH16(), baseB, 1024, RemapH32(), sm, acc);

    int lane = threadIdx.x & 31, warp = threadIdx.x >> 5;
    int wm = warp >> 2, wn = warp & 3;
    uint32_t* P = (uint32_t*)g_P_cat;
#pragma unroll
    for (int mt = 0; mt < 4; mt++) {
#pragma unroll
        for (int j = 0; j < 8; j++) {
            int c = wn * 64 + j * 8 + (lane & 3) * 2;
            float bb0 = Wkb[t * 256 + c], bb1 = Wkb[t * 256 + c + 1];
#pragma unroll
            for (int h = 0; h < 2; h++) {
                int a = by * 128 + wm * 64 + mt * 16 + h * 8 + (lane >> 2);
                float v0 = acc[mt][j][h * 2 + 0] + bb0;
                float v1 = acc[mt][j][h * 2 + 1] + bb1;
                __nv_bfloat16 h0 = __float2bfloat16(v0);
                __nv_bfloat16 h1 = __float2bfloat16(v1);
                __nv_bfloat16 l0 = __float2bfloat16(v0 - __bfloat162float(h0));
                __nv_bfloat16 l1 = __float2bfloat16(v1 - __bfloat162float(h1));
                size_t e = ((size_t)z * 512 + a) * 512 + c;
                P[e >> 1] = (uint32_t)__bfloat16_as_ushort(h0) | ((uint32_t)__bfloat16_as_ushort(h1) << 16);
                P[(e + 256) >> 1] = (uint32_t)__bfloat16_as_ushort(l0) | ((uint32_t)__bfloat16_as_ushort(l1) << 16);
            }
        }
    }
}

// ======================= scores GEMM (128x256, K'=768) + softmax partials =======================
__global__ __launch_bounds__(256, 1) void scores_g(const int* __restrict__ tptr) {
    extern __shared__ __align__(16) char sm[];
    int bx = blockIdx.x;   // a tile 0..1 (256 cols)
    int by = blockIdx.y;   // b tile 0..3
    int z = blockIdx.z;
    int t = z >> 3, w = z & 7;
    int ts = *tptr;
    int base = min(ts + 1, Ln - Wn);
    int u = min(ts + 1 + t, Ln - Wn) - base + w;
    const __nv_bfloat16* baseA = g_E_cat + ((size_t)u * 512 + by * 128) * 512;
    const __nv_bfloat16* baseB = g_P_cat + ((size_t)z * 512 + bx * 256) * 512;
    float acc[4][8][4];
    gemm_core<24, 256>(baseA, 512, RemapH8(), baseB, 512, RemapH16(), sm, acc);

    int tid = threadIdx.x, lane = tid & 31, warp = tid >> 5;
    int wm = warp >> 2, wn = warp & 3;
    float* smx = (float*)sm;            // [4][128]
    float* sms = (float*)(sm + 2048);
    __syncthreads();
    bool dtile = (by == bx * 2) || (by == bx * 2 + 1);
#pragma unroll
    for (int mt = 0; mt < 4; mt++) {
#pragma unroll
        for (int h = 0; h < 2; h++) {
            int row = wm * 64 + mt * 16 + h * 8 + (lane >> 2);
            float mx = -1e30f;
#pragma unroll
            for (int j = 0; j < 8; j++)
                mx = fmaxf(mx, fmaxf(acc[mt][j][h * 2], acc[mt][j][h * 2 + 1]));
            mx = fmaxf(mx, __shfl_xor_sync(0xFFFFFFFFu, mx, 1));
            mx = fmaxf(mx, __shfl_xor_sync(0xFFFFFFFFu, mx, 2));
            float s = 0.f;
#pragma unroll
            for (int j = 0; j < 8; j++) {
                s += __expf(acc[mt][j][h * 2] - mx);
                s += __expf(acc[mt][j][h * 2 + 1] - mx);
            }
            s += __shfl_xor_sync(0xFFFFFFFFu, s, 1);
            s += __shfl_xor_sync(0xFFFFFFFFu, s, 2);
            if ((lane & 3) == 0) { smx[wn * 128 + row] = mx; sms[wn * 128 + row] = s; }
            if (dtile) {
                int bglob = by * 128 + row;
#pragma unroll
                for (int j = 0; j < 8; j++) {
                    int aglob = bx * 256 + wn * 64 + j * 8 + (lane & 3) * 2;
                    if (aglob == bglob)
                        g_diag[(size_t)z * 512 + bglob] = acc[mt][j][h * 2];
                    else if (aglob + 1 == bglob)
                        g_diag[(size_t)z * 512 + bglob] = acc[mt][j][h * 2 + 1];
                }
            }
        }
    }
    __syncthreads();
    if (tid < 128) {
        float m0 = smx[tid], m1 = smx[128 + tid], m2 = smx[256 + tid], m3 = smx[384 + tid];
        float M = fmaxf(fmaxf(m0, m1), fmaxf(m2, m3));
        float S = sms[tid] * __expf(m0 - M) + sms[128 + tid] * __expf(m1 - M)
                + sms[256 + tid] * __expf(m2 - M) + sms[384 + tid] * __expf(m3 - M);
        size_t o = ((size_t)z * 2 + bx) * 512 + by * 128 + tid;
        g_pm[o] = M;
        g_ps[o] = S;
    }
}

// ======================= h1 GEMM (128x128, K'=1536) =======================
// h1[i, c] = ct_flat[i,:] . pw1[c,:] + pb1[c]
__global__ __launch_bounds__(256, 1) void h1_g(const float* __restrict__ pb1) {
    extern __shared__ __align__(16) char sm[];
    int by = blockIdx.x;   // 0..31
    const __nv_bfloat16* baseA = g_ct_cat + (size_t)(by * 128) * 1024;
    float acc[4][4][4];
    gemm_core<48, 128>(baseA, 1024, RemapH16(), g_pw1_cat, 1024, RemapH32(), sm, acc);

    int lane = threadIdx.x & 31, warp = threadIdx.x >> 5;
    int wm = warp >> 2, wn = warp & 3;
#pragma unroll
    for (int mt = 0; mt < 4; mt++) {
#pragma unroll
        for (int j = 0; j < 4; j++) {
            int c = wn * 32 + j * 8 + (lane & 3) * 2;
            float bb0 = pb1[c], bb1 = pb1[c + 1];
#pragma unroll
            for (int h = 0; h < 2; h++) {
                int row = by * 128 + wm * 64 + mt * 16 + h * 8 + (lane >> 2);
                g_h1[(size_t)row * 128 + c]     = acc[mt][j][h * 2 + 0] + bb0;
                g_h1[(size_t)row * 128 + c + 1] = acc[mt][j][h * 2 + 1] + bb1;
            }
        }
    }
}

// ======================= NCE reduction =======================
__global__ void nce_combine_k() {
    int idx = blockIdx.x * 256 + threadIdx.x;   // z*512 + b
    int z = idx >> 9, b = idx & 511;
    float m0 = g_pm[((size_t)z * 2 + 0) * 512 + b];
    float m1 = g_pm[((size_t)z * 2 + 1) * 512 + b];
    float M = fmaxf(m0, m1);
    float S = g_ps[((size_t)z * 2 + 0) * 512 + b] * expf(m0 - M)
            + g_ps[((size_t)z * 2 + 1) * 512 + b] * expf(m1 - M);
    float term = g_diag[idx] - (M + logf(S));
    __shared__ float smr[256];
    smr[threadIdx.x] = term;
    __syncthreads();
    for (int o = 128; o; o >>= 1) {
        if (threadIdx.x < o) smr[threadIdx.x] += smr[threadIdx.x + o];
        __syncthreads();
    }
    if (threadIdx.x == 0) g_part[blockIdx.x] = smr[0];
}

__global__ void nce_final_k(float* __restrict__ out) {
    __shared__ float smr[256];
    smr[threadIdx.x] = g_part[threadIdx.x];
    __syncthreads();
    for (int o = 128; o; o >>= 1) {
        if (threadIdx.x < o) smr[threadIdx.x] += smr[threadIdx.x + o];
        __syncthreads();
    }
    if (threadIdx.x == 0) out[0] = -smr[0] / (float)(Bn * Tn * Wn);
}

// ======================= BN + proj =======================
__global__ void bn_k() {
    int j = blockIdx.x;
    float s1 = 0.f, s2 = 0.f;
    for (int i = threadIdx.x; i < Bn * Wn; i += 256) {
        float v = g_h1[(size_t)i * (Cn / 2) + j];
        s1 += v; s2 += v * v;
    }
    __shared__ float a1[256], a2[256];
    a1[threadIdx.x] = s1; a2[threadIdx.x] = s2;
    __syncthreads();
    for (int o = 128; o; o >>= 1) {
        if (threadIdx.x < o) { a1[threadIdx.x] += a1[threadIdx.x + o]; a2[threadIdx.x] += a2[threadIdx.x + o]; }
        __syncthreads();
    }
    if (threadIdx.x == 0) {
        float mean = a1[0] / (float)(Bn * Wn);
        float var = a2[0] / (float)(Bn * Wn) - mean * mean;
        g_mean[j] = mean;
        g_rstd[j] = rsqrtf(var + 1e-5f);
    }
}

__global__ void proj_k(const float* __restrict__ gamma, const float* __restrict__ beta,
                       const float* __restrict__ pw2, const float* __restrict__ pb2,
                       float* __restrict__ out) {
    __shared__ float smr[Cn / 2];
    int i = blockIdx.x, t = threadIdx.x;  // blockDim = 64
#pragma unroll
    for (int r = 0; r < 2; r++) {
        int j = t + r * 64;
        float v = g_h1[(size_t)i * (Cn / 2) + j];
        v = (v - g_mean[j]) * g_rstd[j] * gamma[j] + beta[j];
        smr[j] = fmaxf(v, 0.f);
    }
    __syncthreads();
    float acc = pb2[t];
    const float* wrow = pw2 + (size_t)t * (Cn / 2);
#pragma unroll 8
    for (int jj = 0; jj < Cn / 2; jj++) acc += smr[jj] * wrow[jj];
    out[1 + (size_t)i * 64 + t] = acc;
}

// ======================= launch =======================
#define SMEM_256 (4 * (128 + 256) * ROWB)   // 122880
#define SMEM_128 (4 * (128 + 128) * ROWB)   // 81920

extern "C" void kernel_launch(void* const* d_in, const int* in_sizes, int n_in,
                              void* d_out, int out_size) {
    const float* features = (const float*)d_in[0];
    const float* c_t      = (const float*)d_in[1];
    const float* Wk_w     = (const float*)d_in[2];
    const float* Wk_b     = (const float*)d_in[3];
    const float* pw1      = (const float*)d_in[4];
    const float* pb1      = (const float*)d_in[5];
    const float* gamma    = (const float*)d_in[6];
    const float* beta     = (const float*)d_in[7];
    const float* pw2      = (const float*)d_in[8];
    const float* pb2      = (const float*)d_in[9];
    const int*   tptr     = (const int*)d_in[10];
    float* out = (float*)d_out;

    static int configured = 0;
    if (!configured) {
        cudaFuncSetAttribute(pred_g, cudaFuncAttributeMaxDynamicSharedMemorySize, SMEM_256);
        cudaFuncSetAttribute(scores_g, cudaFuncAttributeMaxDynamicSharedMemorySize, SMEM_256);
        cudaFuncSetAttribute(h1_g, cudaFuncAttributeMaxDynamicSharedMemorySize, SMEM_128);
        configured = 1;
    }

    split_ct_k<<<(Bn * Wn * Hn) / 256, 256>>>(c_t);
    split_wk_k<<<(Tn * Cn * Hn) / 256, 256>>>(Wk_w);
    split_pw1_k<<<(128 * 512) / 256, 256>>>(pw1);
    gather_split_k<<<Bn, Cn>>>(features, tptr);

    pred_g<<<dim3(4, Zn), 256, SMEM_256>>>(Wk_b);
    h1_g<<<32, 256, SMEM_128>>>(pb1);
    scores_g<<<dim3(2, 4, Zn), 256, SMEM_256>>>(tptr);

    nce_combine_k<<<256, 256>>>();
    nce_final_k<<<1, 256>>>(out);
    bn_k<<<Cn / 2, 256>>>();
    proj_k<<<Bn * Wn, 64>>>(gamma, beta, pw2, pb2, out);
}

// round 5
// speedup vs baseline: 2.4084x; 1.2782x over previous
#include <cuda_runtime.h>
#include <cuda_fp16.h>
#include <cstdint>

#define Bn 512
#define Cn 256
#define Ln 256
#define Hn 512
#define Tn 16
#define Wn 8
#define NU (Tn + Wn - 1)   // 23 distinct encode slices
#define Zn (Tn * Wn)       // 128

// ---------------- scratch (device globals) ----------------
// ct_cat [4096][1024] half: [0,512)=hi, [512,1024)=lo (exact split)
// wk_half [4096][512] half (rounded)
// pw1_half [128][512] half (rounded)
// E_half [23*512][256] half (rounded)
// P_cat [128*512][512] half: [0,256)=hi, [256,512)=lo (exact split of pred result)
__device__ __align__(256) __half g_ct_cat[Bn * Wn * 1024];
__device__ __align__(256) __half g_wk_half[Tn * Cn * 512];
__device__ __align__(256) __half g_pw1_half[128 * 512];
__device__ __align__(256) __half g_E_half[NU * Bn * 256];
__device__ __align__(256) __half g_P_cat[(size_t)Zn * Bn * 512];
__device__ float g_pm[(size_t)Zn * 2 * Bn];
__device__ float g_ps[(size_t)Zn * 2 * Bn];
__device__ float g_diag[(size_t)Zn * Bn];
__device__ float g_h1[Bn * Wn * (Cn / 2)];
__device__ float g_mean[Cn / 2];
__device__ float g_rstd[Cn / 2];
__device__ float g_part[256];

// ======================= helpers =======================
__device__ __forceinline__ uint32_t smem_to_u32(const void* p) {
    uint32_t a;
    asm("{ .reg .u64 t; cvta.to.shared.u64 t, %1; cvt.u32.u64 %0, t; }" : "=r"(a) : "l"(p));
    return a;
}
__device__ __forceinline__ void cp16(uint32_t s, const void* g) {
    asm volatile("cp.async.cg.shared.global [%0], [%1], 16;" :: "r"(s), "l"(g));
}
__device__ __forceinline__ void ldsm4(uint32_t* r, uint32_t addr) {
    asm volatile("ldmatrix.sync.aligned.m8n8.x4.shared.b16 {%0,%1,%2,%3}, [%4];"
        : "=r"(r[0]), "=r"(r[1]), "=r"(r[2]), "=r"(r[3]) : "r"(addr));
}
__device__ __forceinline__ void mma16816(float* d, const uint32_t* a, uint32_t b0, uint32_t b1) {
    asm volatile("mma.sync.aligned.m16n8k16.row.col.f32.f16.f16.f32 "
        "{%0,%1,%2,%3}, {%4,%5,%6,%7}, {%8,%9}, {%0,%1,%2,%3};"
        : "+f"(d[0]), "+f"(d[1]), "+f"(d[2]), "+f"(d[3])
        : "r"(a[0]), "r"(a[1]), "r"(a[2]), "r"(a[3]), "r"(b0), "r"(b1));
}

struct RemapId  { __device__ int operator()(int c) const { return c; } };
struct RemapH8  { __device__ int operator()(int c) const { return c < 8  ? c : c - 8;  } };
struct RemapH16 { __device__ int operator()(int c) const { return c < 16 ? c : c - 16; } };

// rows of 32 halves (64B) padded to 80B -> conflict-free ldmatrix
#define ROWB 80

// ======================= templated GEMM core =======================
// C[128 x NB] += A[128, K'] * B[NB, K'] (NT), K' = NCH*32, 4-stage cp.async pipeline.
template<int NCH, int NB, typename FA, typename FB>
__device__ __forceinline__ void gemm_core(
    const __half* __restrict__ baseA, int strideA, FA remapA,
    const __half* __restrict__ baseB, int strideB, FB remapB,
    char* smem, float (&acc)[4][NB / 32][4])
{
    constexpr int STAGE = (128 + NB) * ROWB;
    constexpr int NJ = NB / 32;
    constexpr int NT = NB / 64;
    uint32_t smb = smem_to_u32(smem);
    int tid = threadIdx.x, lane = tid & 31, warp = tid >> 5;
    int wm = warp >> 2, wn = warp & 3;
    constexpr int WNW = NB / 4;

#pragma unroll
    for (int mt = 0; mt < 4; mt++)
#pragma unroll
        for (int j = 0; j < NJ; j++)
#pragma unroll
            for (int q = 0; q < 4; q++) acc[mt][j][q] = 0.f;

    auto issue = [&](int ch, int stg) {
        int ka = remapA(ch) * 32, kb = remapB(ch) * 32;
        uint32_t s0 = smb + stg * STAGE;
#pragma unroll
        for (int i = 0; i < 2; i++) {
            int idx = tid + 256 * i, r = idx >> 2, q = idx & 3;
            cp16(s0 + r * ROWB + q * 16, baseA + (size_t)r * strideA + ka + q * 8);
        }
#pragma unroll
        for (int i = 0; i < NB / 64; i++) {
            int idx = tid + 256 * i, r = idx >> 2, q = idx & 3;
            cp16(s0 + 128 * ROWB + r * ROWB + q * 16, baseB + (size_t)r * strideB + kb + q * 8);
        }
        asm volatile("cp.async.commit_group;");
    };

    issue(0, 0); issue(1, 1); issue(2, 2);
    for (int ch = 0; ch < NCH; ch++) {
        int stg = ch & 3;
        asm volatile("cp.async.wait_group 2;");
        __syncthreads();
        if (ch + 3 < NCH) issue(ch + 3, (ch + 3) & 3);
        else asm volatile("cp.async.commit_group;");
        uint32_t A0 = smb + stg * STAGE;
        uint32_t B0 = A0 + 128 * ROWB;
#pragma unroll
        for (int kk = 0; kk < 2; kk++) {
            uint32_t af[4][4];
#pragma unroll
            for (int mt = 0; mt < 4; mt++)
                ldsm4(af[mt], A0 + (wm * 64 + mt * 16 + (lane & 15)) * ROWB
                            + (kk * 16 + (lane >> 4) * 8) * 2);
            uint32_t bfr[NT][4];
#pragma unroll
            for (int nt = 0; nt < NT; nt++) {
                int rowb = wn * WNW + nt * 16 + (lane & 7) + ((lane >> 4) << 3);
                int colb = ((lane >> 3) & 1) * 8 + kk * 16;
                ldsm4(bfr[nt], B0 + rowb * ROWB + colb * 2);
            }
#pragma unroll
            for (int mt = 0; mt < 4; mt++)
#pragma unroll
                for (int j = 0; j < NJ; j++) {
                    int nt = j >> 1, h = j & 1;
                    mma16816(acc[mt][j], af[mt], bfr[nt][2 * h], bfr[nt][2 * h + 1]);
                }
        }
        __syncthreads();
    }
}

// ======================= conversion kernels =======================
__global__ void split_ct_k(const float* __restrict__ src) {   // [4096][512]
    int i = blockIdx.x * 256 + threadIdx.x;
    int row = i >> 9, col = i & 511;
    float x = src[i];
    __half h = __float2half(x);
    __half l = __float2half(x - __half2float(h));
    size_t o = (size_t)row * 1024 + col;
    g_ct_cat[o] = h; g_ct_cat[o + 512] = l;
}
__global__ void round_wk_k(const float* __restrict__ src) {   // [4096][512]
    int i = blockIdx.x * 256 + threadIdx.x;
    g_wk_half[i] = __float2half(src[i]);
}
__global__ void round_pw1_k(const float* __restrict__ src) {  // [128][512]
    int i = blockIdx.x * 256 + threadIdx.x;
    g_pw1_half[i] = __float2half(src[i]);
}
__global__ void gather_round_k(const float* __restrict__ f, const int* __restrict__ tptr) {
    int b = blockIdx.x;
    int c = threadIdx.x;  // 256
    int ts = *tptr;
    int base = min(ts + 1, Ln - Wn);
    const float* p = f + (size_t)b * Cn * Ln + (size_t)c * Ln;
#pragma unroll
    for (int u = 0; u < NU; u++) {
        float v = (base + u < Ln) ? p[base + u] : 0.f;
        g_E_half[((size_t)u * Bn + b) * 256 + c] = __float2half(v);
    }
}

// ======================= pred GEMM (128x256, K'=1024) =======================
// per z=(t,w): P[a, c] = ct[a,w,:] . Wk[t,c,:] + Wk_b[t,c]; P stored exact hi|lo fp16.
__global__ __launch_bounds__(256, 1) void pred_g(const float* __restrict__ Wkb) {
    extern __shared__ __align__(16) char sm[];
    int by = blockIdx.x;   // a tile 0..3
    int z = blockIdx.y;
    int t = z >> 3, w = z & 7;
    const __half* baseA = g_ct_cat + ((size_t)(by * 128) * 8 + w) * 1024;
    const __half* baseB = g_wk_half + (size_t)(t * 256) * 512;
    float acc[4][8][4];
    gemm_core<32, 256>(baseA, 8 * 1024, RemapId(), baseB, 512, RemapH16(), sm, acc);

    int lane = threadIdx.x & 31, warp = threadIdx.x >> 5;
    int wm = warp >> 2, wn = warp & 3;
    uint32_t* P = (uint32_t*)g_P_cat;
#pragma unroll
    for (int mt = 0; mt < 4; mt++) {
#pragma unroll
        for (int j = 0; j < 8; j++) {
            int c = wn * 64 + j * 8 + (lane & 3) * 2;
            float bb0 = Wkb[t * 256 + c], bb1 = Wkb[t * 256 + c + 1];
#pragma unroll
            for (int h = 0; h < 2; h++) {
                int a = by * 128 + wm * 64 + mt * 16 + h * 8 + (lane >> 2);
                float v0 = acc[mt][j][h * 2 + 0] + bb0;
                float v1 = acc[mt][j][h * 2 + 1] + bb1;
                __half h0 = __float2half(v0);
                __half h1 = __float2half(v1);
                __half l0 = __float2half(v0 - __half2float(h0));
                __half l1 = __float2half(v1 - __half2float(h1));
                size_t e = ((size_t)z * 512 + a) * 512 + c;
                P[e >> 1] = (uint32_t)__half_as_ushort(h0) | ((uint32_t)__half_as_ushort(h1) << 16);
                P[(e + 256) >> 1] = (uint32_t)__half_as_ushort(l0) | ((uint32_t)__half_as_ushort(l1) << 16);
            }
        }
    }
}

// ======================= scores GEMM (128x256, K'=512) + softmax partials =======================
// S[b, a] = E[u][b,:] . P[z][a,:]
__global__ __launch_bounds__(256, 1) void scores_g(const int* __restrict__ tptr) {
    extern __shared__ __align__(16) char sm[];
    int bx = blockIdx.x;   // a tile 0..1 (256 cols)
    int by = blockIdx.y;   // b tile 0..3
    int z = blockIdx.z;
    int t = z >> 3, w = z & 7;
    int ts = *tptr;
    int base = min(ts + 1, Ln - Wn);
    int u = min(ts + 1 + t, Ln - Wn) - base + w;
    const __half* baseA = g_E_half + ((size_t)u * 512 + by * 128) * 256;
    const __half* baseB = g_P_cat + ((size_t)z * 512 + bx * 256) * 512;
    float acc[4][8][4];
    gemm_core<16, 256>(baseA, 256, RemapH8(), baseB, 512, RemapId(), sm, acc);

    int tid = threadIdx.x, lane = tid & 31, warp = tid >> 5;
    int wm = warp >> 2, wn = warp & 3;
    float* smx = (float*)sm;            // [4][128]
    float* sms = (float*)(sm + 2048);
    __syncthreads();
    bool dtile = (by == bx * 2) || (by == bx * 2 + 1);
#pragma unroll
    for (int mt = 0; mt < 4; mt++) {
#pragma unroll
        for (int h = 0; h < 2; h++) {
            int row = wm * 64 + mt * 16 + h * 8 + (lane >> 2);
            float mx = -1e30f;
#pragma unroll
            for (int j = 0; j < 8; j++)
                mx = fmaxf(mx, fmaxf(acc[mt][j][h * 2], acc[mt][j][h * 2 + 1]));
            mx = fmaxf(mx, __shfl_xor_sync(0xFFFFFFFFu, mx, 1));
            mx = fmaxf(mx, __shfl_xor_sync(0xFFFFFFFFu, mx, 2));
            float s = 0.f;
#pragma unroll
            for (int j = 0; j < 8; j++) {
                s += __expf(acc[mt][j][h * 2] - mx);
                s += __expf(acc[mt][j][h * 2 + 1] - mx);
            }
            s += __shfl_xor_sync(0xFFFFFFFFu, s, 1);
            s += __shfl_xor_sync(0xFFFFFFFFu, s, 2);
            if ((lane & 3) == 0) { smx[wn * 128 + row] = mx; sms[wn * 128 + row] = s; }
            if (dtile) {
                int bglob = by * 128 + row;
#pragma unroll
                for (int j = 0; j < 8; j++) {
                    int aglob = bx * 256 + wn * 64 + j * 8 + (lane & 3) * 2;
                    if (aglob == bglob)
                        g_diag[(size_t)z * 512 + bglob] = acc[mt][j][h * 2];
                    else if (aglob + 1 == bglob)
                        g_diag[(size_t)z * 512 + bglob] = acc[mt][j][h * 2 + 1];
                }
            }
        }
    }
    __syncthreads();
    if (tid < 128) {
        float m0 = smx[tid], m1 = smx[128 + tid], m2 = smx[256 + tid], m3 = smx[384 + tid];
        float M = fmaxf(fmaxf(m0, m1), fmaxf(m2, m3));
        float S = sms[tid] * __expf(m0 - M) + sms[128 + tid] * __expf(m1 - M)
                + sms[256 + tid] * __expf(m2 - M) + sms[384 + tid] * __expf(m3 - M);
        size_t o = ((size_t)z * 2 + bx) * 512 + by * 128 + tid;
        g_pm[o] = M;
        g_ps[o] = S;
    }
}

// ======================= h1 GEMM (128x128, K'=1024) =======================
__global__ __launch_bounds__(256, 1) void h1_g(const float* __restrict__ pb1) {
    extern __shared__ __align__(16) char sm[];
    int by = blockIdx.x;   // 0..31
    const __half* baseA = g_ct_cat + (size_t)(by * 128) * 1024;
    float acc[4][4][4];
    gemm_core<32, 128>(baseA, 1024, RemapId(), g_pw1_half, 512, RemapH16(), sm, acc);

    int lane = threadIdx.x & 31, warp = threadIdx.x >> 5;
    int wm = warp >> 2, wn = warp & 3;
#pragma unroll
    for (int mt = 0; mt < 4; mt++) {
#pragma unroll
        for (int j = 0; j < 4; j++) {
            int c = wn * 32 + j * 8 + (lane & 3) * 2;
            float bb0 = pb1[c], bb1 = pb1[c + 1];
#pragma unroll
            for (int h = 0; h < 2; h++) {
                int row = by * 128 + wm * 64 + mt * 16 + h * 8 + (lane >> 2);
                g_h1[(size_t)row * 128 + c]     = acc[mt][j][h * 2 + 0] + bb0;
                g_h1[(size_t)row * 128 + c + 1] = acc[mt][j][h * 2 + 1] + bb1;
            }
        }
    }
}

// ======================= NCE reduction =======================
__global__ void nce_combine_k() {
    int idx = blockIdx.x * 256 + threadIdx.x;   // z*512 + b
    int z = idx >> 9, b = idx & 511;
    float m0 = g_pm[((size_t)z * 2 + 0) * 512 + b];
    float m1 = g_pm[((size_t)z * 2 + 1) * 512 + b];
    float M = fmaxf(m0, m1);
    float S = g_ps[((size_t)z * 2 + 0) * 512 + b] * expf(m0 - M)
            + g_ps[((size_t)z * 2 + 1) * 512 + b] * expf(m1 - M);
    float term = g_diag[idx] - (M + logf(S));
    __shared__ float smr[256];
    smr[threadIdx.x] = term;
    __syncthreads();
    for (int o = 128; o; o >>= 1) {
        if (threadIdx.x < o) smr[threadIdx.x] += smr[threadIdx.x + o];
        __syncthreads();
    }
    if (threadIdx.x == 0) g_part[blockIdx.x] = smr[0];
}

__global__ void nce_final_k(float* __restrict__ out) {
    __shared__ float smr[256];
    smr[threadIdx.x] = g_part[threadIdx.x];
    __syncthreads();
    for (int o = 128; o; o >>= 1) {
        if (threadIdx.x < o) smr[threadIdx.x] += smr[threadIdx.x + o];
        __syncthreads();
    }
    if (threadIdx.x == 0) out[0] = -smr[0] / (float)(Bn * Tn * Wn);
}

// ======================= BN + proj =======================
__global__ void bn_k() {
    int j = blockIdx.x;
    float s1 = 0.f, s2 = 0.f;
    for (int i = threadIdx.x; i < Bn * Wn; i += 256) {
        float v = g_h1[(size_t)i * (Cn / 2) + j];
        s1 += v; s2 += v * v;
    }
    __shared__ float a1[256], a2[256];
    a1[threadIdx.x] = s1; a2[threadIdx.x] = s2;
    __syncthreads();
    for (int o = 128; o; o >>= 1) {
        if (threadIdx.x < o) { a1[threadIdx.x] += a1[threadIdx.x + o]; a2[threadIdx.x] += a2[threadIdx.x + o]; }
        __syncthreads();
    }
    if (threadIdx.x == 0) {
        float mean = a1[0] / (float)(Bn * Wn);
        float var = a2[0] / (float)(Bn * Wn) - mean * mean;
        g_mean[j] = mean;
        g_rstd[j] = rsqrtf(var + 1e-5f);
    }
}

__global__ void proj_k(const float* __restrict__ gamma, const float* __restrict__ beta,
                       const float* __restrict__ pw2, const float* __restrict__ pb2,
                       float* __restrict__ out) {
    __shared__ float smr[Cn / 2];
    int i = blockIdx.x, t = threadIdx.x;  // blockDim = 64
#pragma unroll
    for (int r = 0; r < 2; r++) {
        int j = t + r * 64;
        float v = g_h1[(size_t)i * (Cn / 2) + j];
        v = (v - g_mean[j]) * g_rstd[j] * gamma[j] + beta[j];
        smr[j] = fmaxf(v, 0.f);
    }
    __syncthreads();
    float acc = pb2[t];
    const float* wrow = pw2 + (size_t)t * (Cn / 2);
#pragma unroll 8
    for (int jj = 0; jj < Cn / 2; jj++) acc += smr[jj] * wrow[jj];
    out[1 + (size_t)i * 64 + t] = acc;
}

// ======================= launch =======================
#define SMEM_256 (4 * (128 + 256) * ROWB)   // 122880
#define SMEM_128 (4 * (128 + 128) * ROWB)   // 81920

extern "C" void kernel_launch(void* const* d_in, const int* in_sizes, int n_in,
                              void* d_out, int out_size) {
    const float* features = (const float*)d_in[0];
    const float* c_t      = (const float*)d_in[1];
    const float* Wk_w     = (const float*)d_in[2];
    const float* Wk_b     = (const float*)d_in[3];
    const float* pw1      = (const float*)d_in[4];
    const float* pb1      = (const float*)d_in[5];
    const float* gamma    = (const float*)d_in[6];
    const float* beta     = (const float*)d_in[7];
    const float* pw2      = (const float*)d_in[8];
    const float* pb2      = (const float*)d_in[9];
    const int*   tptr     = (const int*)d_in[10];
    float* out = (float*)d_out;

    static int configured = 0;
    if (!configured) {
        cudaFuncSetAttribute(pred_g, cudaFuncAttributeMaxDynamicSharedMemorySize, SMEM_256);
        cudaFuncSetAttribute(scores_g, cudaFuncAttributeMaxDynamicSharedMemorySize, SMEM_256);
        cudaFuncSetAttribute(h1_g, cudaFuncAttributeMaxDynamicSharedMemorySize, SMEM_128);
        configured = 1;
    }

    split_ct_k<<<(Bn * Wn * Hn) / 256, 256>>>(c_t);
    round_wk_k<<<(Tn * Cn * Hn) / 256, 256>>>(Wk_w);
    round_pw1_k<<<(128 * 512) / 256, 256>>>(pw1);
    gather_round_k<<<Bn, Cn>>>(features, tptr);

    pred_g<<<dim3(4, Zn), 256, SMEM_256>>>(Wk_b);
    h1_g<<<32, 256, SMEM_128>>>(pb1);
    scores_g<<<dim3(2, 4, Zn), 256, SMEM_256>>>(tptr);

    nce_combine_k<<<256, 256>>>();
    nce_final_k<<<1, 256>>>(out);
    bn_k<<<Cn / 2, 256>>>();
    proj_k<<<Bn * Wn, 64>>>(gamma, beta, pw2, pb2, out);
}

// round 6
// speedup vs baseline: 3.3309x; 1.3830x over previous
#include <cuda_runtime.h>
#include <cuda_fp16.h>
#include <cstdint>

#define Bn 512
#define Cn 256
#define Ln 256
#define Hn 512
#define Tn 16
#define Wn 8
#define NU (Tn + Wn - 1)   // 23 distinct encode slices
#define Zn (Tn * Wn)       // 128

// ---------------- scratch (device globals) ----------------
// ct_cat [4096][1024] half: [0,512)=hi, [512,1024)=lo (exact split; hi also = rounded ct)
// wk_half [4096][512] half (rounded)
// pw1_half [128][512] half (rounded)
// E_half [23*512][256] half (rounded)
// P_half [128*512][256] half (rounded pred result)
__device__ __align__(256) __half g_ct_cat[Bn * Wn * 1024];
__device__ __align__(256) __half g_wk_half[Tn * Cn * 512];
__device__ __align__(256) __half g_pw1_half[128 * 512];
__device__ __align__(256) __half g_E_half[NU * Bn * 256];
__device__ __align__(256) __half g_P_half[(size_t)Zn * Bn * 256];
__device__ float g_pm[(size_t)Zn * 2 * Bn];
__device__ float g_ps[(size_t)Zn * 2 * Bn];
__device__ float g_diag[(size_t)Zn * Bn];
__device__ float g_h1[Bn * Wn * (Cn / 2)];
__device__ float g_mean[Cn / 2];
__device__ float g_rstd[Cn / 2];
__device__ float g_part[256];

// ======================= helpers =======================
__device__ __forceinline__ uint32_t smem_to_u32(const void* p) {
    uint32_t a;
    asm("{ .reg .u64 t; cvta.to.shared.u64 t, %1; cvt.u32.u64 %0, t; }" : "=r"(a) : "l"(p));
    return a;
}
__device__ __forceinline__ void cp16(uint32_t s, const void* g) {
    asm volatile("cp.async.cg.shared.global [%0], [%1], 16;" :: "r"(s), "l"(g));
}
__device__ __forceinline__ void ldsm4(uint32_t* r, uint32_t addr) {
    asm volatile("ldmatrix.sync.aligned.m8n8.x4.shared.b16 {%0,%1,%2,%3}, [%4];"
        : "=r"(r[0]), "=r"(r[1]), "=r"(r[2]), "=r"(r[3]) : "r"(addr));
}
__device__ __forceinline__ void mma16816(float* d, const uint32_t* a, uint32_t b0, uint32_t b1) {
    asm volatile("mma.sync.aligned.m16n8k16.row.col.f32.f16.f16.f32 "
        "{%0,%1,%2,%3}, {%4,%5,%6,%7}, {%8,%9}, {%0,%1,%2,%3};"
        : "+f"(d[0]), "+f"(d[1]), "+f"(d[2]), "+f"(d[3])
        : "r"(a[0]), "r"(a[1]), "r"(a[2]), "r"(a[3]), "r"(b0), "r"(b1));
}

struct RemapId  { __device__ int operator()(int c) const { return c; } };
struct RemapH16 { __device__ int operator()(int c) const { return c < 16 ? c : c - 16; } };

// rows of 32 halves (64B) padded to 80B -> conflict-free ldmatrix
#define ROWB 80

// ======================= templated GEMM core =======================
// C[128 x NB] += A[128, K'] * B[NB, K'] (NT), K' = NCH*32, 4-stage cp.async pipeline.
template<int NCH, int NB, typename FA, typename FB>
__device__ __forceinline__ void gemm_core(
    const __half* __restrict__ baseA, int strideA, FA remapA,
    const __half* __restrict__ baseB, int strideB, FB remapB,
    char* smem, float (&acc)[4][NB / 32][4])
{
    constexpr int STAGE = (128 + NB) * ROWB;
    constexpr int NJ = NB / 32;
    constexpr int NT = NB / 64;
    uint32_t smb = smem_to_u32(smem);
    int tid = threadIdx.x, lane = tid & 31, warp = tid >> 5;
    int wm = warp >> 2, wn = warp & 3;
    constexpr int WNW = NB / 4;

#pragma unroll
    for (int mt = 0; mt < 4; mt++)
#pragma unroll
        for (int j = 0; j < NJ; j++)
#pragma unroll
            for (int q = 0; q < 4; q++) acc[mt][j][q] = 0.f;

    auto issue = [&](int ch, int stg) {
        int ka = remapA(ch) * 32, kb = remapB(ch) * 32;
        uint32_t s0 = smb + stg * STAGE;
#pragma unroll
        for (int i = 0; i < 2; i++) {
            int idx = tid + 256 * i, r = idx >> 2, q = idx & 3;
            cp16(s0 + r * ROWB + q * 16, baseA + (size_t)r * strideA + ka + q * 8);
        }
#pragma unroll
        for (int i = 0; i < NB / 64; i++) {
            int idx = tid + 256 * i, r = idx >> 2, q = idx & 3;
            cp16(s0 + 128 * ROWB + r * ROWB + q * 16, baseB + (size_t)r * strideB + kb + q * 8);
        }
        asm volatile("cp.async.commit_group;");
    };

    issue(0, 0); issue(1, 1); issue(2, 2);
    for (int ch = 0; ch < NCH; ch++) {
        int stg = ch & 3;
        asm volatile("cp.async.wait_group 2;");
        __syncthreads();
        if (ch + 3 < NCH) issue(ch + 3, (ch + 3) & 3);
        else asm volatile("cp.async.commit_group;");
        uint32_t A0 = smb + stg * STAGE;
        uint32_t B0 = A0 + 128 * ROWB;
#pragma unroll
        for (int kk = 0; kk < 2; kk++) {
            uint32_t af[4][4];
#pragma unroll
            for (int mt = 0; mt < 4; mt++)
                ldsm4(af[mt], A0 + (wm * 64 + mt * 16 + (lane & 15)) * ROWB
                            + (kk * 16 + (lane >> 4) * 8) * 2);
            uint32_t bfr[NT][4];
#pragma unroll
            for (int nt = 0; nt < NT; nt++) {
                int rowb = wn * WNW + nt * 16 + (lane & 7) + ((lane >> 4) << 3);
                int colb = ((lane >> 3) & 1) * 8 + kk * 16;
                ldsm4(bfr[nt], B0 + rowb * ROWB + colb * 2);
            }
#pragma unroll
            for (int mt = 0; mt < 4; mt++)
#pragma unroll
                for (int j = 0; j < NJ; j++) {
                    int nt = j >> 1, h = j & 1;
                    mma16816(acc[mt][j], af[mt], bfr[nt][2 * h], bfr[nt][2 * h + 1]);
                }
        }
        __syncthreads();
    }
}

// ======================= conversion kernels =======================
__global__ void split_ct_k(const float* __restrict__ src) {   // [4096][512]
    int i = blockIdx.x * 256 + threadIdx.x;
    int row = i >> 9, col = i & 511;
    float x = src[i];
    __half h = __float2half(x);
    __half l = __float2half(x - __half2float(h));
    size_t o = (size_t)row * 1024 + col;
    g_ct_cat[o] = h; g_ct_cat[o + 512] = l;
}
__global__ void round_wk_k(const float* __restrict__ src) {   // [4096][512]
    int i = blockIdx.x * 256 + threadIdx.x;
    g_wk_half[i] = __float2half(src[i]);
}
__global__ void round_pw1_k(const float* __restrict__ src) {  // [128][512]
    int i = blockIdx.x * 256 + threadIdx.x;
    g_pw1_half[i] = __float2half(src[i]);
}
__global__ void gather_round_k(const float* __restrict__ f, const int* __restrict__ tptr) {
    int b = blockIdx.x;
    int c = threadIdx.x;  // 256
    int ts = *tptr;
    int base = min(ts + 1, Ln - Wn);
    const float* p = f + (size_t)b * Cn * Ln + (size_t)c * Ln;
#pragma unroll
    for (int u = 0; u < NU; u++) {
        float v = (base + u < Ln) ? p[base + u] : 0.f;
        g_E_half[((size_t)u * Bn + b) * 256 + c] = __float2half(v);
    }
}

// ======================= pred GEMM (128x256, K'=512) =======================
// per z=(t,w): P[a, c] = ct[a,w,:] . Wk[t,c,:] + Wk_b[t,c]; P stored rounded fp16.
__global__ __launch_bounds__(256, 1) void pred_g(const float* __restrict__ Wkb) {
    extern __shared__ __align__(16) char sm[];
    int by = blockIdx.x;   // a tile 0..3
    int z = blockIdx.y;
    int t = z >> 3, w = z & 7;
    // A = rounded ct = hi half of ct_cat rows (cols 0..511)
    const __half* baseA = g_ct_cat + ((size_t)(by * 128) * 8 + w) * 1024;
    const __half* baseB = g_wk_half + (size_t)(t * 256) * 512;
    float acc[4][8][4];
    gemm_core<16, 256>(baseA, 8 * 1024, RemapId(), baseB, 512, RemapId(), sm, acc);

    int lane = threadIdx.x & 31, warp = threadIdx.x >> 5;
    int wm = warp >> 2, wn = warp & 3;
    uint32_t* P = (uint32_t*)g_P_half;
#pragma unroll
    for (int mt = 0; mt < 4; mt++) {
#pragma unroll
        for (int j = 0; j < 8; j++) {
            int c = wn * 64 + j * 8 + (lane & 3) * 2;
            float bb0 = Wkb[t * 256 + c], bb1 = Wkb[t * 256 + c + 1];
#pragma unroll
            for (int h = 0; h < 2; h++) {
                int a = by * 128 + wm * 64 + mt * 16 + h * 8 + (lane >> 2);
                __half h0 = __float2half(acc[mt][j][h * 2 + 0] + bb0);
                __half h1 = __float2half(acc[mt][j][h * 2 + 1] + bb1);
                size_t e = ((size_t)z * 512 + a) * 256 + c;
                P[e >> 1] = (uint32_t)__half_as_ushort(h0) | ((uint32_t)__half_as_ushort(h1) << 16);
            }
        }
    }
}

// ======================= scores GEMM (128x256, K'=256) + softmax partials =======================
// S[b, a] = E[u][b,:] . P[z][a,:]
__global__ __launch_bounds__(256, 1) void scores_g(const int* __restrict__ tptr) {
    extern __shared__ __align__(16) char sm[];
    int bx = blockIdx.x;   // a tile 0..1 (256 cols)
    int by = blockIdx.y;   // b tile 0..3
    int z = blockIdx.z;
    int t = z >> 3, w = z & 7;
    int ts = *tptr;
    int base = min(ts + 1, Ln - Wn);
    int u = min(ts + 1 + t, Ln - Wn) - base + w;
    const __half* baseA = g_E_half + ((size_t)u * 512 + by * 128) * 256;
    const __half* baseB = g_P_half + ((size_t)z * 512 + bx * 256) * 256;
    float acc[4][8][4];
    gemm_core<8, 256>(baseA, 256, RemapId(), baseB, 256, RemapId(), sm, acc);

    int tid = threadIdx.x, lane = tid & 31, warp = tid >> 5;
    int wm = warp >> 2, wn = warp & 3;
    float* smx = (float*)sm;            // [4][128]
    float* sms = (float*)(sm + 2048);
    __syncthreads();
    bool dtile = (by == bx * 2) || (by == bx * 2 + 1);
#pragma unroll
    for (int mt = 0; mt < 4; mt++) {
#pragma unroll
        for (int h = 0; h < 2; h++) {
            int row = wm * 64 + mt * 16 + h * 8 + (lane >> 2);
            float mx = -1e30f;
#pragma unroll
            for (int j = 0; j < 8; j++)
                mx = fmaxf(mx, fmaxf(acc[mt][j][h * 2], acc[mt][j][h * 2 + 1]));
            mx = fmaxf(mx, __shfl_xor_sync(0xFFFFFFFFu, mx, 1));
            mx = fmaxf(mx, __shfl_xor_sync(0xFFFFFFFFu, mx, 2));
            float s = 0.f;
#pragma unroll
            for (int j = 0; j < 8; j++) {
                s += __expf(acc[mt][j][h * 2] - mx);
                s += __expf(acc[mt][j][h * 2 + 1] - mx);
            }
            s += __shfl_xor_sync(0xFFFFFFFFu, s, 1);
            s += __shfl_xor_sync(0xFFFFFFFFu, s, 2);
            if ((lane & 3) == 0) { smx[wn * 128 + row] = mx; sms[wn * 128 + row] = s; }
            if (dtile) {
                int bglob = by * 128 + row;
#pragma unroll
                for (int j = 0; j < 8; j++) {
                    int aglob = bx * 256 + wn * 64 + j * 8 + (lane & 3) * 2;
                    if (aglob == bglob)
                        g_diag[(size_t)z * 512 + bglob] = acc[mt][j][h * 2];
                    else if (aglob + 1 == bglob)
                        g_diag[(size_t)z * 512 + bglob] = acc[mt][j][h * 2 + 1];
                }
            }
        }
    }
    __syncthreads();
    if (tid < 128) {
        float m0 = smx[tid], m1 = smx[128 + tid], m2 = smx[256 + tid], m3 = smx[384 + tid];
        float M = fmaxf(fmaxf(m0, m1), fmaxf(m2, m3));
        float S = sms[tid] * __expf(m0 - M) + sms[128 + tid] * __expf(m1 - M)
                + sms[256 + tid] * __expf(m2 - M) + sms[384 + tid] * __expf(m3 - M);
        size_t o = ((size_t)z * 2 + bx) * 512 + by * 128 + tid;
        g_pm[o] = M;
        g_ps[o] = S;
    }
}

// ======================= h1 GEMM (128x128, K'=1024, 2-term exact ct) =======================
__global__ __launch_bounds__(256, 1) void h1_g(const float* __restrict__ pb1) {
    extern __shared__ __align__(16) char sm[];
    int by = blockIdx.x;   // 0..31
    const __half* baseA = g_ct_cat + (size_t)(by * 128) * 1024;
    float acc[4][4][4];
    gemm_core<32, 128>(baseA, 1024, RemapId(), g_pw1_half, 512, RemapH16(), sm, acc);

    int lane = threadIdx.x & 31, warp = threadIdx.x >> 5;
    int wm = warp >> 2, wn = warp & 3;
#pragma unroll
    for (int mt = 0; mt < 4; mt++) {
#pragma unroll
        for (int j = 0; j < 4; j++) {
            int c = wn * 32 + j * 8 + (lane & 3) * 2;
            float bb0 = pb1[c], bb1 = pb1[c + 1];
#pragma unroll
            for (int h = 0; h < 2; h++) {
                int row = by * 128 + wm * 64 + mt * 16 + h * 8 + (lane >> 2);
                g_h1[(size_t)row * 128 + c]     = acc[mt][j][h * 2 + 0] + bb0;
                g_h1[(size_t)row * 128 + c + 1] = acc[mt][j][h * 2 + 1] + bb1;
            }
        }
    }
}

// ======================= NCE reduction =======================
__global__ void nce_combine_k() {
    int idx = blockIdx.x * 256 + threadIdx.x;   // z*512 + b
    int z = idx >> 9, b = idx & 511;
    float m0 = g_pm[((size_t)z * 2 + 0) * 512 + b];
    float m1 = g_pm[((size_t)z * 2 + 1) * 512 + b];
    float M = fmaxf(m0, m1);
    float S = g_ps[((size_t)z * 2 + 0) * 512 + b] * expf(m0 - M)
            + g_ps[((size_t)z * 2 + 1) * 512 + b] * expf(m1 - M);
    float term = g_diag[idx] - (M + logf(S));
    __shared__ float smr[256];
    smr[threadIdx.x] = term;
    __syncthreads();
    for (int o = 128; o; o >>= 1) {
        if (threadIdx.x < o) smr[threadIdx.x] += smr[threadIdx.x + o];
        __syncthreads();
    }
    if (threadIdx.x == 0) g_part[blockIdx.x] = smr[0];
}

__global__ void nce_final_k(float* __restrict__ out) {
    __shared__ float smr[256];
    smr[threadIdx.x] = g_part[threadIdx.x];
    __syncthreads();
    for (int o = 128; o; o >>= 1) {
        if (threadIdx.x < o) smr[threadIdx.x] += smr[threadIdx.x + o];
        __syncthreads();
    }
    if (threadIdx.x == 0) out[0] = -smr[0] / (float)(Bn * Tn * Wn);
}

// ======================= BN + proj =======================
__global__ void bn_k() {
    int j = blockIdx.x;
    float s1 = 0.f, s2 = 0.f;
    for (int i = threadIdx.x; i < Bn * Wn; i += 256) {
        float v = g_h1[(size_t)i * (Cn / 2) + j];
        s1 += v; s2 += v * v;
    }
    __shared__ float a1[256], a2[256];
    a1[threadIdx.x] = s1; a2[threadIdx.x] = s2;
    __syncthreads();
    for (int o = 128; o; o >>= 1) {
        if (threadIdx.x < o) { a1[threadIdx.x] += a1[threadIdx.x + o]; a2[threadIdx.x] += a2[threadIdx.x + o]; }
        __syncthreads();
    }
    if (threadIdx.x == 0) {
        float mean = a1[0] / (float)(Bn * Wn);
        float var = a2[0] / (float)(Bn * Wn) - mean * mean;
        g_mean[j] = mean;
        g_rstd[j] = rsqrtf(var + 1e-5f);
    }
}

__global__ void proj_k(const float* __restrict__ gamma, const float* __restrict__ beta,
                       const float* __restrict__ pw2, const float* __restrict__ pb2,
                       float* __restrict__ out) {
    __shared__ float smr[Cn / 2];
    int i = blockIdx.x, t = threadIdx.x;  // blockDim = 64
#pragma unroll
    for (int r = 0; r < 2; r++) {
        int j = t + r * 64;
        float v = g_h1[(size_t)i * (Cn / 2) + j];
        v = (v - g_mean[j]) * g_rstd[j] * gamma[j] + beta[j];
        smr[j] = fmaxf(v, 0.f);
    }
    __syncthreads();
    float acc = pb2[t];
    const float* wrow = pw2 + (size_t)t * (Cn / 2);
#pragma unroll 8
    for (int jj = 0; jj < Cn / 2; jj++) acc += smr[jj] * wrow[jj];
    out[1 + (size_t)i * 64 + t] = acc;
}

// ======================= launch =======================
#define SMEM_256 (4 * (128 + 256) * ROWB)   // 122880
#define SMEM_128 (4 * (128 + 128) * ROWB)   // 81920

extern "C" void kernel_launch(void* const* d_in, const int* in_sizes, int n_in,
                              void* d_out, int out_size) {
    const float* features = (const float*)d_in[0];
    const float* c_t      = (const float*)d_in[1];
    const float* Wk_w     = (const float*)d_in[2];
    const float* Wk_b     = (const float*)d_in[3];
    const float* pw1      = (const float*)d_in[4];
    const float* pb1      = (const float*)d_in[5];
    const float* gamma    = (const float*)d_in[6];
    const float* beta     = (const float*)d_in[7];
    const float* pw2      = (const float*)d_in[8];
    const float* pb2      = (const float*)d_in[9];
    const int*   tptr     = (const int*)d_in[10];
    float* out = (float*)d_out;

    static int configured = 0;
    if (!configured) {
        cudaFuncSetAttribute(pred_g, cudaFuncAttributeMaxDynamicSharedMemorySize, SMEM_256);
        cudaFuncSetAttribute(scores_g, cudaFuncAttributeMaxDynamicSharedMemorySize, SMEM_256);
        cudaFuncSetAttribute(h1_g, cudaFuncAttributeMaxDynamicSharedMemorySize, SMEM_128);
        configured = 1;
    }

    split_ct_k<<<(Bn * Wn * Hn) / 256, 256>>>(c_t);
    round_wk_k<<<(Tn * Cn * Hn) / 256, 256>>>(Wk_w);
    round_pw1_k<<<(128 * 512) / 256, 256>>>(pw1);
    gather_round_k<<<Bn, Cn>>>(features, tptr);

    pred_g<<<dim3(4, Zn), 256, SMEM_256>>>(Wk_b);
    h1_g<<<32, 256, SMEM_128>>>(pb1);
    scores_g<<<dim3(2, 4, Zn), 256, SMEM_256>>>(tptr);

    nce_combine_k<<<256, 256>>>();
    nce_final_k<<<1, 256>>>(out);
    bn_k<<<Cn / 2, 256>>>();
    proj_k<<<Bn * Wn, 64>>>(gamma, beta, pw2, pb2, out);
}

// round 7
// speedup vs baseline: 3.7542x; 1.1271x over previous
#include <cuda_runtime.h>
#include <cuda_fp16.h>
#include <cstdint>

#define Bn 512
#define Cn 256
#define Ln 256
#define Hn 512
#define Tn 16
#define Wn 8
#define NU (Tn + Wn - 1)   // 23 distinct encode slices
#define Zn (Tn * Wn)       // 128

// ---------------- scratch (device globals) ----------------
__device__ __align__(256) __half g_ct_cat[Bn * Wn * 1024];   // [0,512)=hi, [512,1024)=lo
__device__ __align__(256) __half g_wk_half[Tn * Cn * 512];
__device__ __align__(256) __half g_pw1_half[128 * 512];
__device__ __align__(256) __half g_E_half[NU * Bn * 256];
__device__ __align__(256) __half g_P_half[(size_t)Zn * Bn * 256];
__device__ float g_pm[(size_t)Zn * 2 * Bn];
__device__ float g_ps[(size_t)Zn * 2 * Bn];
__device__ float g_diag[(size_t)Zn * Bn];
__device__ float g_h1[Bn * Wn * (Cn / 2)];
__device__ float g_mean[Cn / 2];
__device__ float g_rstd[Cn / 2];
__device__ float g_part[256];

// ======================= helpers =======================
__device__ __forceinline__ uint32_t smem_to_u32(const void* p) {
    uint32_t a;
    asm("{ .reg .u64 t; cvta.to.shared.u64 t, %1; cvt.u32.u64 %0, t; }" : "=r"(a) : "l"(p));
    return a;
}
__device__ __forceinline__ void cp16(uint32_t s, const void* g) {
    asm volatile("cp.async.cg.shared.global [%0], [%1], 16;" :: "r"(s), "l"(g));
}
__device__ __forceinline__ void ldsm4(uint32_t* r, uint32_t addr) {
    asm volatile("ldmatrix.sync.aligned.m8n8.x4.shared.b16 {%0,%1,%2,%3}, [%4];"
        : "=r"(r[0]), "=r"(r[1]), "=r"(r[2]), "=r"(r[3]) : "r"(addr));
}
__device__ __forceinline__ void mma16816(float* d, const uint32_t* a, uint32_t b0, uint32_t b1) {
    asm volatile("mma.sync.aligned.m16n8k16.row.col.f32.f16.f16.f32 "
        "{%0,%1,%2,%3}, {%4,%5,%6,%7}, {%8,%9}, {%0,%1,%2,%3};"
        : "+f"(d[0]), "+f"(d[1]), "+f"(d[2]), "+f"(d[3])
        : "r"(a[0]), "r"(a[1]), "r"(a[2]), "r"(a[3]), "r"(b0), "r"(b1));
}

struct RemapId  { __device__ int operator()(int c) const { return c; } };
struct RemapH16 { __device__ int operator()(int c) const { return c < 16 ? c : c - 16; } };

#define ROWB 80

// ======================= templated GEMM core =======================
template<int NCH, int NB, typename FA, typename FB>
__device__ __forceinline__ void gemm_core(
    const __half* __restrict__ baseA, int strideA, FA remapA,
    const __half* __restrict__ baseB, int strideB, FB remapB,
    char* smem, float (&acc)[4][NB / 32][4])
{
    constexpr int STAGE = (128 + NB) * ROWB;
    constexpr int NJ = NB / 32;
    constexpr int NT = NB / 64;
    uint32_t smb = smem_to_u32(smem);
    int tid = threadIdx.x, lane = tid & 31, warp = tid >> 5;
    int wm = warp >> 2, wn = warp & 3;
    constexpr int WNW = NB / 4;

#pragma unroll
    for (int mt = 0; mt < 4; mt++)
#pragma unroll
        for (int j = 0; j < NJ; j++)
#pragma unroll
            for (int q = 0; q < 4; q++) acc[mt][j][q] = 0.f;

    auto issue = [&](int ch, int stg) {
        int ka = remapA(ch) * 32, kb = remapB(ch) * 32;
        uint32_t s0 = smb + stg * STAGE;
#pragma unroll
        for (int i = 0; i < 2; i++) {
            int idx = tid + 256 * i, r = idx >> 2, q = idx & 3;
            cp16(s0 + r * ROWB + q * 16, baseA + (size_t)r * strideA + ka + q * 8);
        }
#pragma unroll
        for (int i = 0; i < NB / 64; i++) {
            int idx = tid + 256 * i, r = idx >> 2, q = idx & 3;
            cp16(s0 + 128 * ROWB + r * ROWB + q * 16, baseB + (size_t)r * strideB + kb + q * 8);
        }
        asm volatile("cp.async.commit_group;");
    };

    issue(0, 0); issue(1, 1); issue(2, 2);
    for (int ch = 0; ch < NCH; ch++) {
        int stg = ch & 3;
        asm volatile("cp.async.wait_group 2;");
        __syncthreads();
        if (ch + 3 < NCH) issue(ch + 3, (ch + 3) & 3);
        else asm volatile("cp.async.commit_group;");
        uint32_t A0 = smb + stg * STAGE;
        uint32_t B0 = A0 + 128 * ROWB;
#pragma unroll
        for (int kk = 0; kk < 2; kk++) {
            uint32_t af[4][4];
#pragma unroll
            for (int mt = 0; mt < 4; mt++)
                ldsm4(af[mt], A0 + (wm * 64 + mt * 16 + (lane & 15)) * ROWB
                            + (kk * 16 + (lane >> 4) * 8) * 2);
            uint32_t bfr[NT][4];
#pragma unroll
            for (int nt = 0; nt < NT; nt++) {
                int rowb = wn * WNW + nt * 16 + (lane & 7) + ((lane >> 4) << 3);
                int colb = ((lane >> 3) & 1) * 8 + kk * 16;
                ldsm4(bfr[nt], B0 + rowb * ROWB + colb * 2);
            }
#pragma unroll
            for (int mt = 0; mt < 4; mt++)
#pragma unroll
                for (int j = 0; j < NJ; j++) {
                    int nt = j >> 1, h = j & 1;
                    mma16816(acc[mt][j], af[mt], bfr[nt][2 * h], bfr[nt][2 * h + 1]);
                }
        }
        __syncthreads();
    }
}

// ======================= conversion kernels =======================
__global__ void split_ct_k(const float* __restrict__ src) {   // [4096][512]
    int i = blockIdx.x * 256 + threadIdx.x;
    int row = i >> 9, col = i & 511;
    float x = src[i];
    __half h = __float2half(x);
    __half l = __float2half(x - __half2float(h));
    size_t o = (size_t)row * 1024 + col;
    g_ct_cat[o] = h; g_ct_cat[o + 512] = l;
}
__global__ void round_wk_k(const float* __restrict__ src) {   // [4096][512]
    int i = blockIdx.x * 256 + threadIdx.x;
    g_wk_half[i] = __float2half(src[i]);
}
__global__ void round_pw1_k(const float* __restrict__ src) {  // [128][512]
    int i = blockIdx.x * 256 + threadIdx.x;
    g_pw1_half[i] = __float2half(src[i]);
}

// coalesced gather: per block b, warp-contiguous L-dim reads -> smem -> coalesced writes
__global__ void gather_round_k(const float* __restrict__ f, const int* __restrict__ tptr) {
    __shared__ float st[256][25];   // pad 25 -> conflict-free both phases
    int b = blockIdx.x;
    int tid = threadIdx.x, warp = tid >> 5, lane = tid & 31;
    int ts = *tptr;
    int basel = min(ts + 1, Ln - Wn);
#pragma unroll
    for (int c0 = 0; c0 < 256; c0 += 8) {
        int c = c0 + warp;
        if (lane < NU) {
            int l = basel + lane;
            st[c][lane] = (l < Ln) ? f[(size_t)b * Cn * Ln + (size_t)c * Ln + l] : 0.f;
        }
    }
    __syncthreads();
#pragma unroll
    for (int u = 0; u < NU; u++) {
        g_E_half[((size_t)u * Bn + b) * 256 + tid] = __float2half(st[tid][u]);
    }
}

// ======================= pred GEMM (128x256, K'=512) =======================
__global__ __launch_bounds__(256, 1) void pred_g(const float* __restrict__ Wkb) {
    extern __shared__ __align__(16) char sm[];
    int by = blockIdx.x;   // a tile 0..3
    int z = blockIdx.y;
    int t = z >> 3, w = z & 7;
    const __half* baseA = g_ct_cat + ((size_t)(by * 128) * 8 + w) * 1024;
    const __half* baseB = g_wk_half + (size_t)(t * 256) * 512;
    float acc[4][8][4];
    gemm_core<16, 256>(baseA, 8 * 1024, RemapId(), baseB, 512, RemapId(), sm, acc);

    int lane = threadIdx.x & 31, warp = threadIdx.x >> 5;
    int wm = warp >> 2, wn = warp & 3;
    uint32_t* P = (uint32_t*)g_P_half;
#pragma unroll
    for (int mt = 0; mt < 4; mt++) {
#pragma unroll
        for (int j = 0; j < 8; j++) {
            int c = wn * 64 + j * 8 + (lane & 3) * 2;
            float bb0 = Wkb[t * 256 + c], bb1 = Wkb[t * 256 + c + 1];
#pragma unroll
            for (int h = 0; h < 2; h++) {
                int a = by * 128 + wm * 64 + mt * 16 + h * 8 + (lane >> 2);
                __half h0 = __float2half(acc[mt][j][h * 2 + 0] + bb0);
                __half h1 = __float2half(acc[mt][j][h * 2 + 1] + bb1);
                size_t e = ((size_t)z * 512 + a) * 256 + c;
                P[e >> 1] = (uint32_t)__half_as_ushort(h0) | ((uint32_t)__half_as_ushort(h1) << 16);
            }
        }
    }
}

// ======================= scores GEMM (128x256, K'=256) + softmax partials =======================
__global__ __launch_bounds__(256, 1) void scores_g(const int* __restrict__ tptr) {
    extern __shared__ __align__(16) char sm[];
    int bx = blockIdx.x;   // a tile 0..1 (256 cols)
    int by = blockIdx.y;   // b tile 0..3
    int z = blockIdx.z;
    int t = z >> 3, w = z & 7;
    int ts = *tptr;
    int base = min(ts + 1, Ln - Wn);
    int u = min(ts + 1 + t, Ln - Wn) - base + w;
    const __half* baseA = g_E_half + ((size_t)u * 512 + by * 128) * 256;
    const __half* baseB = g_P_half + ((size_t)z * 512 + bx * 256) * 256;
    float acc[4][8][4];
    gemm_core<8, 256>(baseA, 256, RemapId(), baseB, 256, RemapId(), sm, acc);

    int tid = threadIdx.x, lane = tid & 31, warp = tid >> 5;
    int wm = warp >> 2, wn = warp & 3;
    float* smx = (float*)sm;            // [4][128]
    float* sms = (float*)(sm + 2048);
    __syncthreads();
    bool dtile = (by == bx * 2) || (by == bx * 2 + 1);
#pragma unroll
    for (int mt = 0; mt < 4; mt++) {
#pragma unroll
        for (int h = 0; h < 2; h++) {
            int row = wm * 64 + mt * 16 + h * 8 + (lane >> 2);
            float mx = -1e30f;
#pragma unroll
            for (int j = 0; j < 8; j++)
                mx = fmaxf(mx, fmaxf(acc[mt][j][h * 2], acc[mt][j][h * 2 + 1]));
            mx = fmaxf(mx, __shfl_xor_sync(0xFFFFFFFFu, mx, 1));
            mx = fmaxf(mx, __shfl_xor_sync(0xFFFFFFFFu, mx, 2));
            float s = 0.f;
#pragma unroll
            for (int j = 0; j < 8; j++) {
                s += __expf(acc[mt][j][h * 2] - mx);
                s += __expf(acc[mt][j][h * 2 + 1] - mx);
            }
            s += __shfl_xor_sync(0xFFFFFFFFu, s, 1);
            s += __shfl_xor_sync(0xFFFFFFFFu, s, 2);
            if ((lane & 3) == 0) { smx[wn * 128 + row] = mx; sms[wn * 128 + row] = s; }
            if (dtile) {
                int bglob = by * 128 + row;
#pragma unroll
                for (int j = 0; j < 8; j++) {
                    int aglob = bx * 256 + wn * 64 + j * 8 + (lane & 3) * 2;
                    if (aglob == bglob)
                        g_diag[(size_t)z * 512 + bglob] = acc[mt][j][h * 2];
                    else if (aglob + 1 == bglob)
                        g_diag[(size_t)z * 512 + bglob] = acc[mt][j][h * 2 + 1];
                }
            }
        }
    }
    __syncthreads();
    if (tid < 128) {
        float m0 = smx[tid], m1 = smx[128 + tid], m2 = smx[256 + tid], m3 = smx[384 + tid];
        float M = fmaxf(fmaxf(m0, m1), fmaxf(m2, m3));
        float S = sms[tid] * __expf(m0 - M) + sms[128 + tid] * __expf(m1 - M)
                + sms[256 + tid] * __expf(m2 - M) + sms[384 + tid] * __expf(m3 - M);
        size_t o = ((size_t)z * 2 + bx) * 512 + by * 128 + tid;
        g_pm[o] = M;
        g_ps[o] = S;
    }
}

// ======================= h1 GEMM (128x128, K'=1024, 2-term exact ct) =======================
__global__ __launch_bounds__(256, 1) void h1_g(const float* __restrict__ pb1) {
    extern __shared__ __align__(16) char sm[];
    int by = blockIdx.x;   // 0..31
    const __half* baseA = g_ct_cat + (size_t)(by * 128) * 1024;
    float acc[4][4][4];
    gemm_core<32, 128>(baseA, 1024, RemapId(), g_pw1_half, 512, RemapH16(), sm, acc);

    int lane = threadIdx.x & 31, warp = threadIdx.x >> 5;
    int wm = warp >> 2, wn = warp & 3;
#pragma unroll
    for (int mt = 0; mt < 4; mt++) {
#pragma unroll
        for (int j = 0; j < 4; j++) {
            int c = wn * 32 + j * 8 + (lane & 3) * 2;
            float bb0 = pb1[c], bb1 = pb1[c + 1];
#pragma unroll
            for (int h = 0; h < 2; h++) {
                int row = by * 128 + wm * 64 + mt * 16 + h * 8 + (lane >> 2);
                g_h1[(size_t)row * 128 + c]     = acc[mt][j][h * 2 + 0] + bb0;
                g_h1[(size_t)row * 128 + c + 1] = acc[mt][j][h * 2 + 1] + bb1;
            }
        }
    }
}

// ======================= NCE reduction =======================
__global__ void nce_combine_k() {
    int idx = blockIdx.x * 256 + threadIdx.x;   // z*512 + b
    int z = idx >> 9, b = idx & 511;
    float m0 = g_pm[((size_t)z * 2 + 0) * 512 + b];
    float m1 = g_pm[((size_t)z * 2 + 1) * 512 + b];
    float M = fmaxf(m0, m1);
    float S = g_ps[((size_t)z * 2 + 0) * 512 + b] * expf(m0 - M)
            + g_ps[((size_t)z * 2 + 1) * 512 + b] * expf(m1 - M);
    float term = g_diag[idx] - (M + logf(S));
    __shared__ float smr[256];
    smr[threadIdx.x] = term;
    __syncthreads();
    for (int o = 128; o; o >>= 1) {
        if (threadIdx.x < o) smr[threadIdx.x] += smr[threadIdx.x + o];
        __syncthreads();
    }
    if (threadIdx.x == 0) g_part[blockIdx.x] = smr[0];
}

__global__ void nce_final_k(float* __restrict__ out) {
    __shared__ float smr[256];
    smr[threadIdx.x] = g_part[threadIdx.x];
    __syncthreads();
    for (int o = 128; o; o >>= 1) {
        if (threadIdx.x < o) smr[threadIdx.x] += smr[threadIdx.x + o];
        __syncthreads();
    }
    if (threadIdx.x == 0) out[0] = -smr[0] / (float)(Bn * Tn * Wn);
}

// ======================= BN + proj =======================
__global__ void bn_k() {
    int j = blockIdx.x;
    float s1 = 0.f, s2 = 0.f;
    for (int i = threadIdx.x; i < Bn * Wn; i += 256) {
        float v = g_h1[(size_t)i * (Cn / 2) + j];
        s1 += v; s2 += v * v;
    }
    __shared__ float a1[256], a2[256];
    a1[threadIdx.x] = s1; a2[threadIdx.x] = s2;
    __syncthreads();
    for (int o = 128; o; o >>= 1) {
        if (threadIdx.x < o) { a1[threadIdx.x] += a1[threadIdx.x + o]; a2[threadIdx.x] += a2[threadIdx.x + o]; }
        __syncthreads();
    }
    if (threadIdx.x == 0) {
        float mean = a1[0] / (float)(Bn * Wn);
        float var = a2[0] / (float)(Bn * Wn) - mean * mean;
        g_mean[j] = mean;
        g_rstd[j] = rsqrtf(var + 1e-5f);
    }
}

__global__ void proj_k(const float* __restrict__ gamma, const float* __restrict__ beta,
                       const float* __restrict__ pw2, const float* __restrict__ pb2,
                       float* __restrict__ out) {
    __shared__ float smr[Cn / 2];
    int i = blockIdx.x, t = threadIdx.x;  // blockDim = 64
#pragma unroll
    for (int r = 0; r < 2; r++) {
        int j = t + r * 64;
        float v = g_h1[(size_t)i * (Cn / 2) + j];
        v = (v - g_mean[j]) * g_rstd[j] * gamma[j] + beta[j];
        smr[j] = fmaxf(v, 0.f);
    }
    __syncthreads();
    float acc = pb2[t];
    const float* wrow = pw2 + (size_t)t * (Cn / 2);
#pragma unroll 8
    for (int jj = 0; jj < Cn / 2; jj++) acc += smr[jj] * wrow[jj];
    out[1 + (size_t)i * 64 + t] = acc;
}

// ======================= launch =======================
#define SMEM_256 (4 * (128 + 256) * ROWB)   // 122880
#define SMEM_128 (4 * (128 + 128) * ROWB)   // 81920

extern "C" void kernel_launch(void* const* d_in, const int* in_sizes, int n_in,
                              void* d_out, int out_size) {
    const float* features = (const float*)d_in[0];
    const float* c_t      = (const float*)d_in[1];
    const float* Wk_w     = (const float*)d_in[2];
    const float* Wk_b     = (const float*)d_in[3];
    const float* pw1      = (const float*)d_in[4];
    const float* pb1      = (const float*)d_in[5];
    const float* gamma    = (const float*)d_in[6];
    const float* beta     = (const float*)d_in[7];
    const float* pw2      = (const float*)d_in[8];
    const float* pb2      = (const float*)d_in[9];
    const int*   tptr     = (const int*)d_in[10];
    float* out = (float*)d_out;

    static cudaStream_t sB;
    static cudaEvent_t eFork, eCt, eGather, eJoin;
    static int inited = 0;
    if (!inited) {
        cudaFuncSetAttribute(pred_g, cudaFuncAttributeMaxDynamicSharedMemorySize, SMEM_256);
        cudaFuncSetAttribute(scores_g, cudaFuncAttributeMaxDynamicSharedMemorySize, SMEM_256);
        cudaFuncSetAttribute(h1_g, cudaFuncAttributeMaxDynamicSharedMemorySize, SMEM_128);
        cudaStreamCreateWithFlags(&sB, cudaStreamNonBlocking);
        cudaEventCreateWithFlags(&eFork, cudaEventDisableTiming);
        cudaEventCreateWithFlags(&eCt, cudaEventDisableTiming);
        cudaEventCreateWithFlags(&eGather, cudaEventDisableTiming);
        cudaEventCreateWithFlags(&eJoin, cudaEventDisableTiming);
        inited = 1;
    }

    // ---- fork side stream ----
    cudaEventRecord(eFork, 0);
    cudaStreamWaitEvent(sB, eFork, 0);

    // main stream: ct split + wk round -> pred
    split_ct_k<<<(Bn * Wn * Hn) / 256, 256>>>(c_t);
    cudaEventRecord(eCt, 0);
    round_wk_k<<<(Tn * Cn * Hn) / 256, 256>>>(Wk_w);
    pred_g<<<dim3(4, Zn), 256, SMEM_256>>>(Wk_b);

    // side stream: gather (for scores), then the whole proj head
    gather_round_k<<<Bn, 256, 0, sB>>>(features, tptr);
    cudaEventRecord(eGather, sB);
    round_pw1_k<<<(128 * 512) / 256, 256, 0, sB>>>(pw1);
    cudaStreamWaitEvent(sB, eCt, 0);
    h1_g<<<32, 256, SMEM_128, sB>>>(pb1);
    bn_k<<<Cn / 2, 256, 0, sB>>>();
    proj_k<<<Bn * Wn, 64, 0, sB>>>(gamma, beta, pw2, pb2, out);
    cudaEventRecord(eJoin, sB);

    // main stream: scores (needs E from side stream) -> nce
    cudaStreamWaitEvent(0, eGather, 0);
    scores_g<<<dim3(2, 4, Zn), 256, SMEM_256>>>(tptr);
    nce_combine_k<<<256, 256>>>();
    nce_final_k<<<1, 256>>>(out);

    // join side stream before returning
    cudaStreamWaitEvent(0, eJoin, 0);
}

// round 8
// speedup vs baseline: 3.9028x; 1.0396x over previous
#include <cuda_runtime.h>
#include <cuda_fp16.h>
#include <cstdint>

#define Bn 512
#define Cn 256
#define Ln 256
#define Hn 512
#define Tn 16
#define Wn 8
#define NU (Tn + Wn - 1)   // 23 distinct encode slices
#define Zn (Tn * Wn)       // 128

// ---------------- scratch (device globals) ----------------
__device__ __align__(256) __half g_ct_cat[Bn * Wn * 1024];   // [0,512)=hi, [512,1024)=lo
__device__ __align__(256) __half g_wk_half[Tn * Cn * 512];
__device__ __align__(256) __half g_pw1_half[128 * 512];
__device__ __align__(256) __half g_E_half[NU * Bn * 256];
__device__ __align__(256) __half g_P_half[(size_t)Zn * Bn * 256];
__device__ float g_pm[(size_t)Zn * 2 * Bn];
__device__ float g_ps[(size_t)Zn * 2 * Bn];
__device__ float g_diag[(size_t)Zn * Bn];
__device__ float g_h1[Bn * Wn * (Cn / 2)];
__device__ float g_mean[Cn / 2];
__device__ float g_rstd[Cn / 2];
__device__ float g_part[256];

// ======================= helpers =======================
__device__ __forceinline__ uint32_t smem_to_u32(const void* p) {
    uint32_t a;
    asm("{ .reg .u64 t; cvta.to.shared.u64 t, %1; cvt.u32.u64 %0, t; }" : "=r"(a) : "l"(p));
    return a;
}
__device__ __forceinline__ void cp16(uint32_t s, const void* g) {
    asm volatile("cp.async.cg.shared.global [%0], [%1], 16;" :: "r"(s), "l"(g));
}
__device__ __forceinline__ void ldsm4(uint32_t* r, uint32_t addr) {
    asm volatile("ldmatrix.sync.aligned.m8n8.x4.shared.b16 {%0,%1,%2,%3}, [%4];"
        : "=r"(r[0]), "=r"(r[1]), "=r"(r[2]), "=r"(r[3]) : "r"(addr));
}
__device__ __forceinline__ void mma16816(float* d, const uint32_t* a, uint32_t b0, uint32_t b1) {
    asm volatile("mma.sync.aligned.m16n8k16.row.col.f32.f16.f16.f32 "
        "{%0,%1,%2,%3}, {%4,%5,%6,%7}, {%8,%9}, {%0,%1,%2,%3};"
        : "+f"(d[0]), "+f"(d[1]), "+f"(d[2]), "+f"(d[3])
        : "r"(a[0]), "r"(a[1]), "r"(a[2]), "r"(a[3]), "r"(b0), "r"(b1));
}

struct RemapId  { __device__ int operator()(int c) const { return c; } };
struct RemapH16 { __device__ int operator()(int c) const { return c < 16 ? c : c - 16; } };

#define ROWB 80

// ======================= 512-thread GEMM core (128x256 tile, 3 stages) =======================
// warp tile 32x64; 16 warps: wm = warp>>2 (m band of 32 rows), wn = warp&3 (64 cols)
template<int NCH, typename FA, typename FB>
__device__ __forceinline__ void gemm_core512(
    const __half* __restrict__ baseA, int strideA, FA remapA,
    const __half* __restrict__ baseB, int strideB, FB remapB,
    char* smem, float (&acc)[2][8][4])
{
    constexpr int STAGE = 384 * ROWB;
    uint32_t smb = smem_to_u32(smem);
    int tid = threadIdx.x, lane = tid & 31, warp = tid >> 5;
    int wm = warp >> 2, wn = warp & 3;

#pragma unroll
    for (int mt = 0; mt < 2; mt++)
#pragma unroll
        for (int j = 0; j < 8; j++)
#pragma unroll
            for (int q = 0; q < 4; q++) acc[mt][j][q] = 0.f;

    auto issue = [&](int ch, int stg) {
        int ka = remapA(ch) * 32, kb = remapB(ch) * 32;
        uint32_t s0 = smb + stg * STAGE;
        {
            int r = tid >> 2, q = tid & 3;
            cp16(s0 + r * ROWB + q * 16, baseA + (size_t)r * strideA + ka + q * 8);
        }
#pragma unroll
        for (int i = 0; i < 2; i++) {
            int idx = tid + 512 * i, r = idx >> 2, q = idx & 3;
            cp16(s0 + 128 * ROWB + r * ROWB + q * 16, baseB + (size_t)r * strideB + kb + q * 8);
        }
        asm volatile("cp.async.commit_group;");
    };

    issue(0, 0); issue(1, 1);
#pragma unroll
    for (int ch = 0; ch < NCH; ch++) {
        int stg = ch % 3;
        asm volatile("cp.async.wait_group 1;");
        __syncthreads();
        int nx = ch + 2;
        if (nx < NCH) issue(nx, nx % 3);
        else asm volatile("cp.async.commit_group;");
        uint32_t A0 = smb + stg * STAGE;
        uint32_t B0 = A0 + 128 * ROWB;
#pragma unroll
        for (int kk = 0; kk < 2; kk++) {
            uint32_t af[2][4];
#pragma unroll
            for (int mt = 0; mt < 2; mt++)
                ldsm4(af[mt], A0 + (wm * 32 + mt * 16 + (lane & 15)) * ROWB
                            + (kk * 16 + (lane >> 4) * 8) * 2);
            uint32_t bfr[4][4];
#pragma unroll
            for (int nt = 0; nt < 4; nt++) {
                int rowb = wn * 64 + nt * 16 + (lane & 7) + ((lane >> 4) << 3);
                int colb = ((lane >> 3) & 1) * 8 + kk * 16;
                ldsm4(bfr[nt], B0 + rowb * ROWB + colb * 2);
            }
#pragma unroll
            for (int mt = 0; mt < 2; mt++)
#pragma unroll
                for (int j = 0; j < 8; j++) {
                    int nt = j >> 1, h = j & 1;
                    mma16816(acc[mt][j], af[mt], bfr[nt][2 * h], bfr[nt][2 * h + 1]);
                }
        }
        __syncthreads();
    }
}

// ======================= 256-thread GEMM core (h1 only; 128x128, 4 stages) =======================
template<int NCH, int NB, typename FA, typename FB>
__device__ __forceinline__ void gemm_core(
    const __half* __restrict__ baseA, int strideA, FA remapA,
    const __half* __restrict__ baseB, int strideB, FB remapB,
    char* smem, float (&acc)[4][NB / 32][4])
{
    constexpr int STAGE = (128 + NB) * ROWB;
    constexpr int NJ = NB / 32;
    constexpr int NT = NB / 64;
    uint32_t smb = smem_to_u32(smem);
    int tid = threadIdx.x, lane = tid & 31, warp = tid >> 5;
    int wm = warp >> 2, wn = warp & 3;
    constexpr int WNW = NB / 4;

#pragma unroll
    for (int mt = 0; mt < 4; mt++)
#pragma unroll
        for (int j = 0; j < NJ; j++)
#pragma unroll
            for (int q = 0; q < 4; q++) acc[mt][j][q] = 0.f;

    auto issue = [&](int ch, int stg) {
        int ka = remapA(ch) * 32, kb = remapB(ch) * 32;
        uint32_t s0 = smb + stg * STAGE;
#pragma unroll
        for (int i = 0; i < 2; i++) {
            int idx = tid + 256 * i, r = idx >> 2, q = idx & 3;
            cp16(s0 + r * ROWB + q * 16, baseA + (size_t)r * strideA + ka + q * 8);
        }
#pragma unroll
        for (int i = 0; i < NB / 64; i++) {
            int idx = tid + 256 * i, r = idx >> 2, q = idx & 3;
            cp16(s0 + 128 * ROWB + r * ROWB + q * 16, baseB + (size_t)r * strideB + kb + q * 8);
        }
        asm volatile("cp.async.commit_group;");
    };

    issue(0, 0); issue(1, 1); issue(2, 2);
    for (int ch = 0; ch < NCH; ch++) {
        int stg = ch & 3;
        asm volatile("cp.async.wait_group 2;");
        __syncthreads();
        if (ch + 3 < NCH) issue(ch + 3, (ch + 3) & 3);
        else asm volatile("cp.async.commit_group;");
        uint32_t A0 = smb + stg * STAGE;
        uint32_t B0 = A0 + 128 * ROWB;
#pragma unroll
        for (int kk = 0; kk < 2; kk++) {
            uint32_t af[4][4];
#pragma unroll
            for (int mt = 0; mt < 4; mt++)
                ldsm4(af[mt], A0 + (wm * 64 + mt * 16 + (lane & 15)) * ROWB
                            + (kk * 16 + (lane >> 4) * 8) * 2);
            uint32_t bfr[NT][4];
#pragma unroll
            for (int nt = 0; nt < NT; nt++) {
                int rowb = wn * WNW + nt * 16 + (lane & 7) + ((lane >> 4) << 3);
                int colb = ((lane >> 3) & 1) * 8 + kk * 16;
                ldsm4(bfr[nt], B0 + rowb * ROWB + colb * 2);
            }
#pragma unroll
            for (int mt = 0; mt < 4; mt++)
#pragma unroll
                for (int j = 0; j < NJ; j++) {
                    int nt = j >> 1, h = j & 1;
                    mma16816(acc[mt][j], af[mt], bfr[nt][2 * h], bfr[nt][2 * h + 1]);
                }
        }
        __syncthreads();
    }
}

// ======================= conversion kernels =======================
__global__ void split_ct_k(const float* __restrict__ src) {   // [4096][512]
    int i = blockIdx.x * 256 + threadIdx.x;
    int row = i >> 9, col = i & 511;
    float x = src[i];
    __half h = __float2half(x);
    __half l = __float2half(x - __half2float(h));
    size_t o = (size_t)row * 1024 + col;
    g_ct_cat[o] = h; g_ct_cat[o + 512] = l;
}
__global__ void round_wk_k(const float* __restrict__ src) {   // [4096][512]
    int i = blockIdx.x * 256 + threadIdx.x;
    g_wk_half[i] = __float2half(src[i]);
}
__global__ void round_pw1_k(const float* __restrict__ src) {  // [128][512]
    int i = blockIdx.x * 256 + threadIdx.x;
    g_pw1_half[i] = __float2half(src[i]);
}

// coalesced gather
__global__ void gather_round_k(const float* __restrict__ f, const int* __restrict__ tptr) {
    __shared__ float st[256][25];
    int b = blockIdx.x;
    int tid = threadIdx.x, warp = tid >> 5, lane = tid & 31;
    int ts = *tptr;
    int basel = min(ts + 1, Ln - Wn);
#pragma unroll
    for (int c0 = 0; c0 < 256; c0 += 8) {
        int c = c0 + warp;
        if (lane < NU) {
            int l = basel + lane;
            st[c][lane] = (l < Ln) ? f[(size_t)b * Cn * Ln + (size_t)c * Ln + l] : 0.f;
        }
    }
    __syncthreads();
#pragma unroll
    for (int u = 0; u < NU; u++) {
        g_E_half[((size_t)u * Bn + b) * 256 + tid] = __float2half(st[tid][u]);
    }
}

// ======================= pred GEMM (512 thr, 128x256, K'=512) =======================
__global__ __launch_bounds__(512, 1) void pred_g(const float* __restrict__ Wkb, int z0) {
    extern __shared__ __align__(16) char sm[];
    int by = blockIdx.x;           // a tile 0..3
    int z = z0 + blockIdx.y;       // 64 per launch
    int t = z >> 3, w = z & 7;
    const __half* baseA = g_ct_cat + ((size_t)(by * 128) * 8 + w) * 1024;
    const __half* baseB = g_wk_half + (size_t)(t * 256) * 512;
    float acc[2][8][4];
    gemm_core512<16>(baseA, 8 * 1024, RemapId(), baseB, 512, RemapId(), sm, acc);

    int lane = threadIdx.x & 31, warp = threadIdx.x >> 5;
    int wm = warp >> 2, wn = warp & 3;
    uint32_t* P = (uint32_t*)g_P_half;
#pragma unroll
    for (int mt = 0; mt < 2; mt++) {
#pragma unroll
        for (int j = 0; j < 8; j++) {
            int c = wn * 64 + j * 8 + (lane & 3) * 2;
            float bb0 = Wkb[t * 256 + c], bb1 = Wkb[t * 256 + c + 1];
#pragma unroll
            for (int h = 0; h < 2; h++) {
                int a = by * 128 + wm * 32 + mt * 16 + h * 8 + (lane >> 2);
                __half h0 = __float2half(acc[mt][j][h * 2 + 0] + bb0);
                __half h1 = __float2half(acc[mt][j][h * 2 + 1] + bb1);
                size_t e = ((size_t)z * 512 + a) * 256 + c;
                P[e >> 1] = (uint32_t)__half_as_ushort(h0) | ((uint32_t)__half_as_ushort(h1) << 16);
            }
        }
    }
}

// ======================= scores GEMM (512 thr, 128x256, K'=256) + softmax partials =======================
__global__ __launch_bounds__(512, 1) void scores_g(const int* __restrict__ tptr, int z0) {
    extern __shared__ __align__(16) char sm[];
    int bx = blockIdx.x;   // a tile 0..1
    int by = blockIdx.y;   // b tile 0..3
    int z = z0 + blockIdx.z;
    int t = z >> 3, w = z & 7;
    int ts = *tptr;
    int base = min(ts + 1, Ln - Wn);
    int u = min(ts + 1 + t, Ln - Wn) - base + w;
    const __half* baseA = g_E_half + ((size_t)u * 512 + by * 128) * 256;
    const __half* baseB = g_P_half + ((size_t)z * 512 + bx * 256) * 256;
    float acc[2][8][4];
    gemm_core512<8>(baseA, 256, RemapId(), baseB, 256, RemapId(), sm, acc);

    int tid = threadIdx.x, lane = tid & 31, warp = tid >> 5;
    int wm = warp >> 2, wn = warp & 3;
    float* smx = (float*)sm;            // [4][128]
    float* sms = (float*)(sm + 2048);
    __syncthreads();
    bool dtile = (by == bx * 2) || (by == bx * 2 + 1);
#pragma unroll
    for (int mt = 0; mt < 2; mt++) {
#pragma unroll
        for (int h = 0; h < 2; h++) {
            int row = wm * 32 + mt * 16 + h * 8 + (lane >> 2);
            float mx = -1e30f;
#pragma unroll
            for (int j = 0; j < 8; j++)
                mx = fmaxf(mx, fmaxf(acc[mt][j][h * 2], acc[mt][j][h * 2 + 1]));
            mx = fmaxf(mx, __shfl_xor_sync(0xFFFFFFFFu, mx, 1));
            mx = fmaxf(mx, __shfl_xor_sync(0xFFFFFFFFu, mx, 2));
            float s = 0.f;
#pragma unroll
            for (int j = 0; j < 8; j++) {
                s += __expf(acc[mt][j][h * 2] - mx);
                s += __expf(acc[mt][j][h * 2 + 1] - mx);
            }
            s += __shfl_xor_sync(0xFFFFFFFFu, s, 1);
            s += __shfl_xor_sync(0xFFFFFFFFu, s, 2);
            if ((lane & 3) == 0) { smx[wn * 128 + row] = mx; sms[wn * 128 + row] = s; }
            if (dtile) {
                int bglob = by * 128 + row;
#pragma unroll
                for (int j = 0; j < 8; j++) {
                    int aglob = bx * 256 + wn * 64 + j * 8 + (lane & 3) * 2;
                    if (aglob == bglob)
                        g_diag[(size_t)z * 512 + bglob] = acc[mt][j][h * 2];
                    else if (aglob + 1 == bglob)
                        g_diag[(size_t)z * 512 + bglob] = acc[mt][j][h * 2 + 1];
                }
            }
        }
    }
    __syncthreads();
    if (tid < 128) {
        float m0 = smx[tid], m1 = smx[128 + tid], m2 = smx[256 + tid], m3 = smx[384 + tid];
        float M = fmaxf(fmaxf(m0, m1), fmaxf(m2, m3));
        float S = sms[tid] * __expf(m0 - M) + sms[128 + tid] * __expf(m1 - M)
                + sms[256 + tid] * __expf(m2 - M) + sms[384 + tid] * __expf(m3 - M);
        size_t o = ((size_t)z * 2 + bx) * 512 + by * 128 + tid;
        g_pm[o] = M;
        g_ps[o] = S;
    }
}

// ======================= h1 GEMM (256 thr, 128x128, K'=1024, 2-term exact ct) =======================
__global__ __launch_bounds__(256, 1) void h1_g(const float* __restrict__ pb1) {
    extern __shared__ __align__(16) char sm[];
    int by = blockIdx.x;   // 0..31
    const __half* baseA = g_ct_cat + (size_t)(by * 128) * 1024;
    float acc[4][4][4];
    gemm_core<32, 128>(baseA, 1024, RemapId(), g_pw1_half, 512, RemapH16(), sm, acc);

    int lane = threadIdx.x & 31, warp = threadIdx.x >> 5;
    int wm = warp >> 2, wn = warp & 3;
#pragma unroll
    for (int mt = 0; mt < 4; mt++) {
#pragma unroll
        for (int j = 0; j < 4; j++) {
            int c = wn * 32 + j * 8 + (lane & 3) * 2;
            float bb0 = pb1[c], bb1 = pb1[c + 1];
#pragma unroll
            for (int h = 0; h < 2; h++) {
                int row = by * 128 + wm * 64 + mt * 16 + h * 8 + (lane >> 2);
                g_h1[(size_t)row * 128 + c]     = acc[mt][j][h * 2 + 0] + bb0;
                g_h1[(size_t)row * 128 + c + 1] = acc[mt][j][h * 2 + 1] + bb1;
            }
        }
    }
}

// ======================= NCE reduction =======================
__global__ void nce_combine_k() {
    int idx = blockIdx.x * 256 + threadIdx.x;   // z*512 + b
    int z = idx >> 9, b = idx & 511;
    float m0 = g_pm[((size_t)z * 2 + 0) * 512 + b];
    float m1 = g_pm[((size_t)z * 2 + 1) * 512 + b];
    float M = fmaxf(m0, m1);
    float S = g_ps[((size_t)z * 2 + 0) * 512 + b] * expf(m0 - M)
            + g_ps[((size_t)z * 2 + 1) * 512 + b] * expf(m1 - M);
    float term = g_diag[idx] - (M + logf(S));
    __shared__ float smr[256];
    smr[threadIdx.x] = term;
    __syncthreads();
    for (int o = 128; o; o >>= 1) {
        if (threadIdx.x < o) smr[threadIdx.x] += smr[threadIdx.x + o];
        __syncthreads();
    }
    if (threadIdx.x == 0) g_part[blockIdx.x] = smr[0];
}

__global__ void nce_final_k(float* __restrict__ out) {
    __shared__ float smr[256];
    smr[threadIdx.x] = g_part[threadIdx.x];
    __syncthreads();
    for (int o = 128; o; o >>= 1) {
        if (threadIdx.x < o) smr[threadIdx.x] += smr[threadIdx.x + o];
        __syncthreads();
    }
    if (threadIdx.x == 0) out[0] = -smr[0] / (float)(Bn * Tn * Wn);
}

// ======================= BN + proj =======================
__global__ void bn_k() {
    int j = blockIdx.x;
    float s1 = 0.f, s2 = 0.f;
    for (int i = threadIdx.x; i < Bn * Wn; i += 256) {
        float v = g_h1[(size_t)i * (Cn / 2) + j];
        s1 += v; s2 += v * v;
    }
    __shared__ float a1[256], a2[256];
    a1[threadIdx.x] = s1; a2[threadIdx.x] = s2;
    __syncthreads();
    for (int o = 128; o; o >>= 1) {
        if (threadIdx.x < o) { a1[threadIdx.x] += a1[threadIdx.x + o]; a2[threadIdx.x] += a2[threadIdx.x + o]; }
        __syncthreads();
    }
    if (threadIdx.x == 0) {
        float mean = a1[0] / (float)(Bn * Wn);
        float var = a2[0] / (float)(Bn * Wn) - mean * mean;
        g_mean[j] = mean;
        g_rstd[j] = rsqrtf(var + 1e-5f);
    }
}

__global__ void proj_k(const float* __restrict__ gamma, const float* __restrict__ beta,
                       const float* __restrict__ pw2, const float* __restrict__ pb2,
                       float* __restrict__ out) {
    __shared__ float smr[Cn / 2];
    int i = blockIdx.x, t = threadIdx.x;  // blockDim = 64
#pragma unroll
    for (int r = 0; r < 2; r++) {
        int j = t + r * 64;
        float v = g_h1[(size_t)i * (Cn / 2) + j];
        v = (v - g_mean[j]) * g_rstd[j] * gamma[j] + beta[j];
        smr[j] = fmaxf(v, 0.f);
    }
    __syncthreads();
    float acc = pb2[t];
    const float* wrow = pw2 + (size_t)t * (Cn / 2);
#pragma unroll 8
    for (int jj = 0; jj < Cn / 2; jj++) acc += smr[jj] * wrow[jj];
    out[1 + (size_t)i * 64 + t] = acc;
}

// ======================= launch =======================
#define SMEM3 (3 * 384 * ROWB)               // 92160 (512-thread cores)
#define SMEM_128 (4 * (128 + 128) * ROWB)    // 81920 (h1)

extern "C" void kernel_launch(void* const* d_in, const int* in_sizes, int n_in,
                              void* d_out, int out_size) {
    const float* features = (const float*)d_in[0];
    const float* c_t      = (const float*)d_in[1];
    const float* Wk_w     = (const float*)d_in[2];
    const float* Wk_b     = (const float*)d_in[3];
    const float* pw1      = (const float*)d_in[4];
    const float* pb1      = (const float*)d_in[5];
    const float* gamma    = (const float*)d_in[6];
    const float* beta     = (const float*)d_in[7];
    const float* pw2      = (const float*)d_in[8];
    const float* pb2      = (const float*)d_in[9];
    const int*   tptr     = (const int*)d_in[10];
    float* out = (float*)d_out;

    static cudaStream_t sB, sC;
    static cudaEvent_t eFork, eCt, eG, eP0, eS0, eJoin;
    static int inited = 0;
    if (!inited) {
        cudaFuncSetAttribute(pred_g, cudaFuncAttributeMaxDynamicSharedMemorySize, SMEM3);
        cudaFuncSetAttribute(scores_g, cudaFuncAttributeMaxDynamicSharedMemorySize, SMEM3);
        cudaFuncSetAttribute(h1_g, cudaFuncAttributeMaxDynamicSharedMemorySize, SMEM_128);
        cudaStreamCreateWithFlags(&sB, cudaStreamNonBlocking);
        cudaStreamCreateWithFlags(&sC, cudaStreamNonBlocking);
        cudaEventCreateWithFlags(&eFork, cudaEventDisableTiming);
        cudaEventCreateWithFlags(&eCt, cudaEventDisableTiming);
        cudaEventCreateWithFlags(&eG, cudaEventDisableTiming);
        cudaEventCreateWithFlags(&eP0, cudaEventDisableTiming);
        cudaEventCreateWithFlags(&eS0, cudaEventDisableTiming);
        cudaEventCreateWithFlags(&eJoin, cudaEventDisableTiming);
        inited = 1;
    }

    // ---- fork ----
    cudaEventRecord(eFork, 0);
    cudaStreamWaitEvent(sB, eFork, 0);
    cudaStreamWaitEvent(sC, eFork, 0);

    // main: ct split -> wk round -> pred halves
    split_ct_k<<<(Bn * Wn * Hn) / 256, 256>>>(c_t);
    cudaEventRecord(eCt, 0);
    round_wk_k<<<(Tn * Cn * Hn) / 256, 256>>>(Wk_w);
    pred_g<<<dim3(4, 64), 512, SMEM3>>>(Wk_b, 0);
    cudaEventRecord(eP0, 0);
    pred_g<<<dim3(4, 64), 512, SMEM3>>>(Wk_b, 64);

    // side B: gather + proj head
    gather_round_k<<<Bn, 256, 0, sB>>>(features, tptr);
    cudaEventRecord(eG, sB);
    round_pw1_k<<<(128 * 512) / 256, 256, 0, sB>>>(pw1);
    cudaStreamWaitEvent(sB, eCt, 0);
    h1_g<<<32, 256, SMEM_128, sB>>>(pb1);
    bn_k<<<Cn / 2, 256, 0, sB>>>();
    proj_k<<<Bn * Wn, 64, 0, sB>>>(gamma, beta, pw2, pb2, out);
    cudaEventRecord(eJoin, sB);

    // side C: scores half 0 overlaps pred half 1
    cudaStreamWaitEvent(sC, eG, 0);
    cudaStreamWaitEvent(sC, eP0, 0);
    scores_g<<<dim3(2, 4, 64), 512, SMEM3, sC>>>(tptr, 0);
    cudaEventRecord(eS0, sC);

    // main: scores half 1 (stream-ordered after pred h1) -> nce
    cudaStreamWaitEvent(0, eG, 0);
    scores_g<<<dim3(2, 4, 64), 512, SMEM3>>>(tptr, 64);
    cudaStreamWaitEvent(0, eS0, 0);
    nce_combine_k<<<256, 256>>>();
    nce_final_k<<<1, 256>>>(out);

    // join
    cudaStreamWaitEvent(0, eJoin, 0);
}

// round 9
// speedup vs baseline: 4.3963x; 1.1265x over previous
#include <cuda_runtime.h>
#include <cuda_fp16.h>
#include <cstdint>

#define Bn 512
#define Cn 256
#define Ln 256
#define Hn 512
#define Tn 16
#define Wn 8
#define NU (Tn + Wn - 1)   // 23 distinct encode slices
#define Zn (Tn * Wn)       // 128

// ---------------- scratch (device globals) ----------------
__device__ __align__(256) __half g_ct_cat[Bn * Wn * 1024];   // [0,512)=hi, [512,1024)=lo
__device__ __align__(256) __half g_wk_half[Tn * Cn * 512];
__device__ __align__(256) __half g_pw1_half[128 * 512];
__device__ __align__(256) __half g_E_half[NU * Bn * 256];
__device__ __align__(256) __half g_P_half[(size_t)Zn * Bn * 256];
__device__ float g_pm[(size_t)Zn * 4 * Bn];
__device__ float g_ps[(size_t)Zn * 4 * Bn];
__device__ float g_diag[(size_t)Zn * Bn];
__device__ float g_h1[Bn * Wn * (Cn / 2)];
__device__ float g_mean[Cn / 2];
__device__ float g_rstd[Cn / 2];
__device__ float g_part[256];

// ======================= helpers =======================
__device__ __forceinline__ uint32_t smem_to_u32(const void* p) {
    uint32_t a;
    asm("{ .reg .u64 t; cvta.to.shared.u64 t, %1; cvt.u32.u64 %0, t; }" : "=r"(a) : "l"(p));
    return a;
}
__device__ __forceinline__ void cp16(uint32_t s, const void* g) {
    asm volatile("cp.async.cg.shared.global [%0], [%1], 16;" :: "r"(s), "l"(g));
}
__device__ __forceinline__ void ldsm4(uint32_t* r, uint32_t addr) {
    asm volatile("ldmatrix.sync.aligned.m8n8.x4.shared.b16 {%0,%1,%2,%3}, [%4];"
        : "=r"(r[0]), "=r"(r[1]), "=r"(r[2]), "=r"(r[3]) : "r"(addr));
}
__device__ __forceinline__ void mma16816(float* d, const uint32_t* a, uint32_t b0, uint32_t b1) {
    asm volatile("mma.sync.aligned.m16n8k16.row.col.f32.f16.f16.f32 "
        "{%0,%1,%2,%3}, {%4,%5,%6,%7}, {%8,%9}, {%0,%1,%2,%3};"
        : "+f"(d[0]), "+f"(d[1]), "+f"(d[2]), "+f"(d[3])
        : "r"(a[0]), "r"(a[1]), "r"(a[2]), "r"(a[3]), "r"(b0), "r"(b1));
}

struct RemapId { __device__ int operator()(int c) const { return c; } };
struct RemapH8 { __device__ int operator()(int c) const { return c < 8 ? c : c - 8; } };

// rows of 64 halves (128B) padded to 144B; 144 mod 128 = 16 -> conflict-free ldsm/cp
#define ROWB 144
#define SMEMC (3 * 256 * ROWB)   // 110592; 2 CTAs/SM = 221184 <= 228KB

// ======================= 256-thread GEMM core: 128x128 tile, K-chunk 64, 3 stages =======================
// 8 warps: wm = warp>>2 (64-row band), wn = warp&3 (32-col band); warp tile 64x32; acc[4][4][4].
template<int NCH, typename FB>
__device__ __forceinline__ void gemm_core256(
    const __half* __restrict__ baseA, int strideA,
    const __half* __restrict__ baseB, int strideB, FB remapB,
    char* smem, float (&acc)[4][4][4])
{
    constexpr int STAGE = 256 * ROWB;
    uint32_t smb = smem_to_u32(smem);
    int tid = threadIdx.x, lane = tid & 31, warp = tid >> 5;
    int wm = warp >> 2, wn = warp & 3;

#pragma unroll
    for (int mt = 0; mt < 4; mt++)
#pragma unroll
        for (int j = 0; j < 4; j++)
#pragma unroll
            for (int q = 0; q < 4; q++) acc[mt][j][q] = 0.f;

    auto issue = [&](int ch, int stg) {
        int ka = ch * 64, kb = remapB(ch) * 64;
        uint32_t s0 = smb + stg * STAGE;
#pragma unroll
        for (int i = 0; i < 4; i++) {
            int idx = tid + 256 * i, r = idx >> 3, q = idx & 7;
            cp16(s0 + r * ROWB + q * 16, baseA + (size_t)r * strideA + ka + q * 8);
        }
#pragma unroll
        for (int i = 0; i < 4; i++) {
            int idx = tid + 256 * i, r = idx >> 3, q = idx & 7;
            cp16(s0 + 128 * ROWB + r * ROWB + q * 16, baseB + (size_t)r * strideB + kb + q * 8);
        }
        asm volatile("cp.async.commit_group;");
    };

    issue(0, 0); issue(1, 1);
#pragma unroll
    for (int ch = 0; ch < NCH; ch++) {
        int stg = ch % 3;
        asm volatile("cp.async.wait_group 1;");
        __syncthreads();
        int nx = ch + 2;
        if (nx < NCH) issue(nx, nx % 3);
        else asm volatile("cp.async.commit_group;");
        uint32_t A0 = smb + stg * STAGE;
        uint32_t B0 = A0 + 128 * ROWB;
#pragma unroll
        for (int kk = 0; kk < 4; kk++) {
            uint32_t af[4][4];
#pragma unroll
            for (int mt = 0; mt < 4; mt++)
                ldsm4(af[mt], A0 + (wm * 64 + mt * 16 + (lane & 15)) * ROWB
                            + (kk * 16 + (lane >> 4) * 8) * 2);
            uint32_t bfr[2][4];
#pragma unroll
            for (int nt = 0; nt < 2; nt++) {
                int rowb = wn * 32 + nt * 16 + (lane & 7) + ((lane >> 4) << 3);
                int colb = ((lane >> 3) & 1) * 8 + kk * 16;
                ldsm4(bfr[nt], B0 + rowb * ROWB + colb * 2);
            }
#pragma unroll
            for (int mt = 0; mt < 4; mt++)
#pragma unroll
                for (int j = 0; j < 4; j++)
                    mma16816(acc[mt][j], af[mt], bfr[j >> 1][2 * (j & 1)], bfr[j >> 1][2 * (j & 1) + 1]);
        }
        __syncthreads();
    }
}

// ======================= conversion kernels =======================
__global__ void split_ct_k(const float* __restrict__ src) {   // [4096][512]
    int i = blockIdx.x * 256 + threadIdx.x;
    int row = i >> 9, col = i & 511;
    float x = src[i];
    __half h = __float2half(x);
    __half l = __float2half(x - __half2float(h));
    size_t o = (size_t)row * 1024 + col;
    g_ct_cat[o] = h; g_ct_cat[o + 512] = l;
}
__global__ void round_wk_k(const float* __restrict__ src) {   // [4096][512]
    int i = blockIdx.x * 256 + threadIdx.x;
    g_wk_half[i] = __float2half(src[i]);
}
__global__ void round_pw1_k(const float* __restrict__ src) {  // [128][512]
    int i = blockIdx.x * 256 + threadIdx.x;
    g_pw1_half[i] = __float2half(src[i]);
}

// coalesced gather
__global__ void gather_round_k(const float* __restrict__ f, const int* __restrict__ tptr) {
    __shared__ float st[256][25];
    int b = blockIdx.x;
    int tid = threadIdx.x, warp = tid >> 5, lane = tid & 31;
    int ts = *tptr;
    int basel = min(ts + 1, Ln - Wn);
#pragma unroll
    for (int c0 = 0; c0 < 256; c0 += 8) {
        int c = c0 + warp;
        if (lane < NU) {
            int l = basel + lane;
            st[c][lane] = (l < Ln) ? f[(size_t)b * Cn * Ln + (size_t)c * Ln + l] : 0.f;
        }
    }
    __syncthreads();
#pragma unroll
    for (int u = 0; u < NU; u++) {
        g_E_half[((size_t)u * Bn + b) * 256 + tid] = __float2half(st[tid][u]);
    }
}

// ======================= pred GEMM (256 thr, 128x128, K'=512) =======================
__global__ __launch_bounds__(256, 2) void pred_g(const float* __restrict__ Wkb, int z0) {
    extern __shared__ __align__(16) char sm[];
    int by = blockIdx.x;           // a tile 0..3
    int bx = blockIdx.y;           // c tile 0..1
    int z = z0 + blockIdx.z;       // 64 per launch
    int t = z >> 3, w = z & 7;
    const __half* baseA = g_ct_cat + ((size_t)(by * 128) * 8 + w) * 1024;
    const __half* baseB = g_wk_half + (size_t)(t * 256 + bx * 128) * 512;
    float acc[4][4][4];
    gemm_core256<8>(baseA, 8 * 1024, baseB, 512, RemapId(), sm, acc);

    int lane = threadIdx.x & 31, warp = threadIdx.x >> 5;
    int wm = warp >> 2, wn = warp & 3;
    uint32_t* P = (uint32_t*)g_P_half;
#pragma unroll
    for (int mt = 0; mt < 4; mt++) {
#pragma unroll
        for (int j = 0; j < 4; j++) {
            int c = bx * 128 + wn * 32 + j * 8 + (lane & 3) * 2;
            float bb0 = Wkb[t * 256 + c], bb1 = Wkb[t * 256 + c + 1];
#pragma unroll
            for (int h = 0; h < 2; h++) {
                int a = by * 128 + wm * 64 + mt * 16 + h * 8 + (lane >> 2);
                __half h0 = __float2half(acc[mt][j][h * 2 + 0] + bb0);
                __half h1 = __float2half(acc[mt][j][h * 2 + 1] + bb1);
                size_t e = ((size_t)z * 512 + a) * 256 + c;
                P[e >> 1] = (uint32_t)__half_as_ushort(h0) | ((uint32_t)__half_as_ushort(h1) << 16);
            }
        }
    }
}

// ======================= scores GEMM (256 thr, 128x128, K'=256) + softmax partials =======================
__global__ __launch_bounds__(256, 2) void scores_g(const int* __restrict__ tptr, int z0) {
    extern __shared__ __align__(16) char sm[];
    int bx = blockIdx.x;   // a tile 0..3
    int by = blockIdx.y;   // b tile 0..3
    int z = z0 + blockIdx.z;
    int t = z >> 3, w = z & 7;
    int ts = *tptr;
    int base = min(ts + 1, Ln - Wn);
    int u = min(ts + 1 + t, Ln - Wn) - base + w;
    const __half* baseA = g_E_half + ((size_t)u * 512 + by * 128) * 256;
    const __half* baseB = g_P_half + ((size_t)z * 512 + bx * 128) * 256;
    float acc[4][4][4];
    gemm_core256<4>(baseA, 256, baseB, 256, RemapId(), sm, acc);

    int tid = threadIdx.x, lane = tid & 31, warp = tid >> 5;
    int wm = warp >> 2, wn = warp & 3;
    float* smx = (float*)sm;            // [4][128]
    float* sms = (float*)(sm + 2048);
    bool dtile = (bx == by);
#pragma unroll
    for (int mt = 0; mt < 4; mt++) {
#pragma unroll
        for (int h = 0; h < 2; h++) {
            int row = wm * 64 + mt * 16 + h * 8 + (lane >> 2);
            float mx = -1e30f;
#pragma unroll
            for (int j = 0; j < 4; j++)
                mx = fmaxf(mx, fmaxf(acc[mt][j][h * 2], acc[mt][j][h * 2 + 1]));
            mx = fmaxf(mx, __shfl_xor_sync(0xFFFFFFFFu, mx, 1));
            mx = fmaxf(mx, __shfl_xor_sync(0xFFFFFFFFu, mx, 2));
            float s = 0.f;
#pragma unroll
            for (int j = 0; j < 4; j++) {
                s += __expf(acc[mt][j][h * 2] - mx);
                s += __expf(acc[mt][j][h * 2 + 1] - mx);
            }
            s += __shfl_xor_sync(0xFFFFFFFFu, s, 1);
            s += __shfl_xor_sync(0xFFFFFFFFu, s, 2);
            if ((lane & 3) == 0) { smx[wn * 128 + row] = mx; sms[wn * 128 + row] = s; }
            if (dtile) {
                int bglob = by * 128 + row;
#pragma unroll
                for (int j = 0; j < 4; j++) {
                    int aglob = bx * 128 + wn * 32 + j * 8 + (lane & 3) * 2;
                    if (aglob == bglob)
                        g_diag[(size_t)z * 512 + bglob] = acc[mt][j][h * 2];
                    else if (aglob + 1 == bglob)
                        g_diag[(size_t)z * 512 + bglob] = acc[mt][j][h * 2 + 1];
                }
            }
        }
    }
    __syncthreads();
    if (tid < 128) {
        float m0 = smx[tid], m1 = smx[128 + tid], m2 = smx[256 + tid], m3 = smx[384 + tid];
        float M = fmaxf(fmaxf(m0, m1), fmaxf(m2, m3));
        float S = sms[tid] * __expf(m0 - M) + sms[128 + tid] * __expf(m1 - M)
                + sms[256 + tid] * __expf(m2 - M) + sms[384 + tid] * __expf(m3 - M);
        size_t o = ((size_t)z * 4 + bx) * 512 + by * 128 + tid;
        g_pm[o] = M;
        g_ps[o] = S;
    }
}

// ======================= h1 GEMM (256 thr, 128x128, K'=1024, 2-term exact ct) =======================
__global__ __launch_bounds__(256, 2) void h1_g(const float* __restrict__ pb1) {
    extern __shared__ __align__(16) char sm[];
    int by = blockIdx.x;   // 0..31
    const __half* baseA = g_ct_cat + (size_t)(by * 128) * 1024;
    float acc[4][4][4];
    gemm_core256<16>(baseA, 1024, g_pw1_half, 512, RemapH8(), sm, acc);

    int lane = threadIdx.x & 31, warp = threadIdx.x >> 5;
    int wm = warp >> 2, wn = warp & 3;
#pragma unroll
    for (int mt = 0; mt < 4; mt++) {
#pragma unroll
        for (int j = 0; j < 4; j++) {
            int c = wn * 32 + j * 8 + (lane & 3) * 2;
            float bb0 = pb1[c], bb1 = pb1[c + 1];
#pragma unroll
            for (int h = 0; h < 2; h++) {
                int row = by * 128 + wm * 64 + mt * 16 + h * 8 + (lane >> 2);
                g_h1[(size_t)row * 128 + c]     = acc[mt][j][h * 2 + 0] + bb0;
                g_h1[(size_t)row * 128 + c + 1] = acc[mt][j][h * 2 + 1] + bb1;
            }
        }
    }
}

// ======================= NCE reduction =======================
__global__ void nce_combine_k() {
    int idx = blockIdx.x * 256 + threadIdx.x;   // z*512 + b
    int z = idx >> 9, b = idx & 511;
    float m[4], p[4];
#pragma unroll
    for (int i = 0; i < 4; i++) {
        m[i] = g_pm[((size_t)z * 4 + i) * 512 + b];
        p[i] = g_ps[((size_t)z * 4 + i) * 512 + b];
    }
    float M = fmaxf(fmaxf(m[0], m[1]), fmaxf(m[2], m[3]));
    float S = p[0] * expf(m[0] - M) + p[1] * expf(m[1] - M)
            + p[2] * expf(m[2] - M) + p[3] * expf(m[3] - M);
    float term = g_diag[idx] - (M + logf(S));
    __shared__ float smr[256];
    smr[threadIdx.x] = term;
    __syncthreads();
    for (int o = 128; o; o >>= 1) {
        if (threadIdx.x < o) smr[threadIdx.x] += smr[threadIdx.x + o];
        __syncthreads();
    }
    if (threadIdx.x == 0) g_part[blockIdx.x] = smr[0];
}

__global__ void nce_final_k(float* __restrict__ out) {
    __shared__ float smr[256];
    smr[threadIdx.x] = g_part[threadIdx.x];
    __syncthreads();
    for (int o = 128; o; o >>= 1) {
        if (threadIdx.x < o) smr[threadIdx.x] += smr[threadIdx.x + o];
        __syncthreads();
    }
    if (threadIdx.x == 0) out[0] = -smr[0] / (float)(Bn * Tn * Wn);
}

// ======================= BN + proj =======================
__global__ void bn_k() {
    int j = blockIdx.x;
    float s1 = 0.f, s2 = 0.f;
    for (int i = threadIdx.x; i < Bn * Wn; i += 256) {
        float v = g_h1[(size_t)i * (Cn / 2) + j];
        s1 += v; s2 += v * v;
    }
    __shared__ float a1[256], a2[256];
    a1[threadIdx.x] = s1; a2[threadIdx.x] = s2;
    __syncthreads();
    for (int o = 128; o; o >>= 1) {
        if (threadIdx.x < o) { a1[threadIdx.x] += a1[threadIdx.x + o]; a2[threadIdx.x] += a2[threadIdx.x + o]; }
        __syncthreads();
    }
    if (threadIdx.x == 0) {
        float mean = a1[0] / (float)(Bn * Wn);
        float var = a2[0] / (float)(Bn * Wn) - mean * mean;
        g_mean[j] = mean;
        g_rstd[j] = rsqrtf(var + 1e-5f);
    }
}

__global__ void proj_k(const float* __restrict__ gamma, const float* __restrict__ beta,
                       const float* __restrict__ pw2, const float* __restrict__ pb2,
                       float* __restrict__ out) {
    __shared__ float smr[Cn / 2];
    int i = blockIdx.x, t = threadIdx.x;  // blockDim = 64
#pragma unroll
    for (int r = 0; r < 2; r++) {
        int j = t + r * 64;
        float v = g_h1[(size_t)i * (Cn / 2) + j];
        v = (v - g_mean[j]) * g_rstd[j] * gamma[j] + beta[j];
        smr[j] = fmaxf(v, 0.f);
    }
    __syncthreads();
    float acc = pb2[t];
    const float* wrow = pw2 + (size_t)t * (Cn / 2);
#pragma unroll 8
    for (int jj = 0; jj < Cn / 2; jj++) acc += smr[jj] * wrow[jj];
    out[1 + (size_t)i * 64 + t] = acc;
}

// ======================= launch =======================
extern "C" void kernel_launch(void* const* d_in, const int* in_sizes, int n_in,
                              void* d_out, int out_size) {
    const float* features = (const float*)d_in[0];
    const float* c_t      = (const float*)d_in[1];
    const float* Wk_w     = (const float*)d_in[2];
    const float* Wk_b     = (const float*)d_in[3];
    const float* pw1      = (const float*)d_in[4];
    const float* pb1      = (const float*)d_in[5];
    const float* gamma    = (const float*)d_in[6];
    const float* beta     = (const float*)d_in[7];
    const float* pw2      = (const float*)d_in[8];
    const float* pb2      = (const float*)d_in[9];
    const int*   tptr     = (const int*)d_in[10];
    float* out = (float*)d_out;

    static cudaStream_t sB, sC;
    static cudaEvent_t eFork, eCt, eG, eP0, eS0, eJoin;
    static int inited = 0;
    if (!inited) {
        cudaFuncSetAttribute(pred_g, cudaFuncAttributeMaxDynamicSharedMemorySize, SMEMC);
        cudaFuncSetAttribute(scores_g, cudaFuncAttributeMaxDynamicSharedMemorySize, SMEMC);
        cudaFuncSetAttribute(h1_g, cudaFuncAttributeMaxDynamicSharedMemorySize, SMEMC);
        cudaStreamCreateWithFlags(&sB, cudaStreamNonBlocking);
        cudaStreamCreateWithFlags(&sC, cudaStreamNonBlocking);
        cudaEventCreateWithFlags(&eFork, cudaEventDisableTiming);
        cudaEventCreateWithFlags(&eCt, cudaEventDisableTiming);
        cudaEventCreateWithFlags(&eG, cudaEventDisableTiming);
        cudaEventCreateWithFlags(&eP0, cudaEventDisableTiming);
        cudaEventCreateWithFlags(&eS0, cudaEventDisableTiming);
        cudaEventCreateWithFlags(&eJoin, cudaEventDisableTiming);
        inited = 1;
    }

    // ---- fork ----
    cudaEventRecord(eFork, 0);
    cudaStreamWaitEvent(sB, eFork, 0);
    cudaStreamWaitEvent(sC, eFork, 0);

    // main: ct split -> wk round -> pred halves
    split_ct_k<<<(Bn * Wn * Hn) / 256, 256>>>(c_t);
    cudaEventRecord(eCt, 0);
    round_wk_k<<<(Tn * Cn * Hn) / 256, 256>>>(Wk_w);
    pred_g<<<dim3(4, 2, 64), 256, SMEMC>>>(Wk_b, 0);
    cudaEventRecord(eP0, 0);
    pred_g<<<dim3(4, 2, 64), 256, SMEMC>>>(Wk_b, 64);

    // side B: gather + proj head
    gather_round_k<<<Bn, 256, 0, sB>>>(features, tptr);
    cudaEventRecord(eG, sB);
    round_pw1_k<<<(128 * 512) / 256, 256, 0, sB>>>(pw1);
    cudaStreamWaitEvent(sB, eCt, 0);
    h1_g<<<32, 256, SMEMC, sB>>>(pb1);
    bn_k<<<Cn / 2, 256, 0, sB>>>();
    proj_k<<<Bn * Wn, 64, 0, sB>>>(gamma, beta, pw2, pb2, out);
    cudaEventRecord(eJoin, sB);

    // side C: scores half 0 overlaps pred half 1
    cudaStreamWaitEvent(sC, eG, 0);
    cudaStreamWaitEvent(sC, eP0, 0);
    scores_g<<<dim3(4, 4, 64), 256, SMEMC, sC>>>(tptr, 0);
    cudaEventRecord(eS0, sC);

    // main: scores half 1 -> nce
    cudaStreamWaitEvent(0, eG, 0);
    scores_g<<<dim3(4, 4, 64), 256, SMEMC>>>(tptr, 64);
    cudaStreamWaitEvent(0, eS0, 0);
    nce_combine_k<<<256, 256>>>();
    nce_final_k<<<1, 256>>>(out);

    // join
    cudaStreamWaitEvent(0, eJoin, 0);
}